// round 5
// baseline (speedup 1.0000x reference)
#include <cuda_runtime.h>
#include <cuda_bf16.h>

#define PI_HALF 1.57079632679489662f
#define NMAX 20000
#define EMAX 300000

// ---------------- scratch (no allocation allowed) ----------------
__device__ float g_bufA[NMAX * 128];
__device__ float g_bufB[NMAX * 128];
__device__ float g_xc[NMAX * 128];
__device__ float g_q[NMAX * 4];
__device__ float g_k[NMAX * 4];
__device__ float g_att[EMAX + NMAX];
__device__ float g_sum[2];
__device__ float g_rot[36 * 8];   // 36 complex 2x2 matrices, 8 floats each

// ---------------- complex helpers ----------------
__device__ __forceinline__ float2 cmul(float2 a, float2 b) {
    return make_float2(a.x * b.x - a.y * b.y, a.x * b.y + a.y * b.x);
}

// Single-qubit gates; M = bit mask of the wire (wire w -> mask 1<<(3-w)).
template<int M>
__device__ __forceinline__ void ap_ry(float2* s, float c, float sn) {
#pragma unroll
    for (int i = 0; i < 16; i++) {
        if (i & M) continue;
        float2 a = s[i], b = s[i | M];
        s[i]     = make_float2(c * a.x - sn * b.x, c * a.y - sn * b.y);
        s[i | M] = make_float2(sn * a.x + c * b.x, sn * a.y + c * b.y);
    }
}

template<int M>
__device__ __forceinline__ void ap_h(float2* s) {
    const float r = 0.70710678118654752f;
#pragma unroll
    for (int i = 0; i < 16; i++) {
        if (i & M) continue;
        float2 a = s[i], b = s[i | M];
        s[i]     = make_float2((a.x + b.x) * r, (a.y + b.y) * r);
        s[i | M] = make_float2((a.x - b.x) * r, (a.y - b.y) * r);
    }
}

template<int MC, int MT>
__device__ __forceinline__ void ap_cry(float2* s, float c, float sn) {
#pragma unroll
    for (int i = 0; i < 16; i++) {
        if (!(i & MC) || (i & MT)) continue;
        float2 a = s[i], b = s[i | MT];
        s[i]      = make_float2(c * a.x - sn * b.x, c * a.y - sn * b.y);
        s[i | MT] = make_float2(sn * a.x + c * b.x, sn * a.y + c * b.y);
    }
}

template<int MC, int MT>
__device__ __forceinline__ void ap_cnot(float2* s) {
#pragma unroll
    for (int i = 0; i < 16; i++) {
        if (!(i & MC) || (i & MT)) continue;
        float2 t = s[i];
        s[i] = s[i | MT];
        s[i | MT] = t;
    }
}

template<int M>
__device__ __forceinline__ void ap_rot(float2* s, const float* __restrict__ u) {
    float2 u00 = make_float2(u[0], u[1]);
    float2 u01 = make_float2(u[2], u[3]);
    float2 u10 = make_float2(u[4], u[5]);
    float2 u11 = make_float2(u[6], u[7]);
#pragma unroll
    for (int i = 0; i < 16; i++) {
        if (i & M) continue;
        float2 a = s[i], b = s[i | M];
        float2 ra = cmul(u00, a), rb = cmul(u01, b);
        float2 sa = cmul(u10, a), sb = cmul(u11, b);
        s[i]     = make_float2(ra.x + rb.x, ra.y + rb.y);
        s[i | M] = make_float2(sa.x + sb.x, sa.y + sb.y);
    }
}

__device__ __forceinline__ void init_state(float2* s) {
#pragma unroll
    for (int i = 0; i < 16; i++) s[i] = make_float2(0.f, 0.f);
    s[0] = make_float2(1.f, 0.f);
}

__device__ __forceinline__ void zexp4(const float2* s, float z[4]) {
    z[0] = z[1] = z[2] = z[3] = 0.f;
#pragma unroll
    for (int i = 0; i < 16; i++) {
        float n = s[i].x * s[i].x + s[i].y * s[i].y;
        z[0] += (i & 8) ? -n : n;
        z[1] += (i & 4) ? -n : n;
        z[2] += (i & 2) ? -n : n;
        z[3] += (i & 1) ? -n : n;
    }
}

__device__ __forceinline__ void ry_all(float2* s, const float a[4]) {
    float c, sn;
    __sincosf(a[0] * 0.5f, &sn, &c); ap_ry<8>(s, c, sn);
    __sincosf(a[1] * 0.5f, &sn, &c); ap_ry<4>(s, c, sn);
    __sincosf(a[2] * 0.5f, &sn, &c); ap_ry<2>(s, c, sn);
    __sincosf(a[3] * 0.5f, &sn, &c); ap_ry<1>(s, c, sn);
}

__device__ __forceinline__ void rot_all(float2* s, const float* __restrict__ rm) {
    ap_rot<8>(s, rm);
    ap_rot<4>(s, rm + 8);
    ap_rot<2>(s, rm + 16);
    ap_rot<1>(s, rm + 24);
}

// ---------------- circuits ----------------
// entangle: RY(x_i); 2x { CNOT(0,1)(1,2)(2,3); Rot all; CNOT(0,3) }; Z exps
__device__ __forceinline__ void entangle_circ(const float xin[4],
                                              const float* __restrict__ rot,
                                              float z[4]) {
    float2 s[16];
    init_state(s);
    ry_all(s, xin);
#pragma unroll
    for (int l = 0; l < 2; l++) {
        ap_cnot<8, 4>(s); ap_cnot<4, 2>(s); ap_cnot<2, 1>(s);
        rot_all(s, rot + l * 32);
        ap_cnot<8, 1>(s);
    }
    zexp4(s, z);
}

// attention: RY(q); H all; CRY(k_i) on (i,(i+1)%4); Rot all; mean of Z exps
__device__ __forceinline__ float att_circ(const float q[4], const float k[4],
                                          const float* __restrict__ rot) {
    float2 s[16];
    init_state(s);
    ry_all(s, q);
    ap_h<8>(s); ap_h<4>(s); ap_h<2>(s); ap_h<1>(s);
    float c, sn;
    __sincosf(k[0] * 0.5f, &sn, &c); ap_cry<8, 4>(s, c, sn);
    __sincosf(k[1] * 0.5f, &sn, &c); ap_cry<4, 2>(s, c, sn);
    __sincosf(k[2] * 0.5f, &sn, &c); ap_cry<2, 1>(s, c, sn);
    __sincosf(k[3] * 0.5f, &sn, &c); ap_cry<1, 8>(s, c, sn);
    rot_all(s, rot);
    float score = 0.f;
#pragma unroll
    for (int i = 0; i < 16; i++) {
        float n = s[i].x * s[i].x + s[i].y * s[i].y;
        score += n * (1.0f - 0.5f * (float)__popc(i));   // mean of 4 Z exps
    }
    return score;
}

// path: H all; RY(x); 3x { Rot all; CNOT(0,1)(1,2)(2,3) }; Z exps
__device__ __forceinline__ void path_circ(const float xin[4],
                                          const float* __restrict__ rot,
                                          float z[4]) {
    float2 s[16];
    init_state(s);
    ap_h<8>(s); ap_h<4>(s); ap_h<2>(s); ap_h<1>(s);
    ry_all(s, xin);
#pragma unroll
    for (int l = 0; l < 3; l++) {
        rot_all(s, rot + l * 32);
        ap_cnot<8, 4>(s); ap_cnot<4, 2>(s); ap_cnot<2, 1>(s);
    }
    zexp4(s, z);
}

// ---------------- kernels ----------------

// Precompute all 36 Rot matrices + zero softmax accumulators.
// matrix t: t<8 att [L=2][4]; 8<=t<24 ent [L=2][2][4]; 24<=t<36 path [3][4]
__global__ void prep_kernel(const float* __restrict__ attqp,
                            const float* __restrict__ entp,
                            const float* __restrict__ pathp,
                            float* __restrict__ rot, float* __restrict__ sums) {
    int t = threadIdx.x;
    if (t < 2) sums[t] = 0.f;
    if (t >= 36) return;
    const float* p;
    if (t < 8)       p = attqp + t * 3;
    else if (t < 24) p = entp + (t - 8) * 3;
    else             p = pathp + (t - 24) * 3;
    float phi = p[0], th = p[1], om = p[2];
    float c, s;  sincosf(th * 0.5f, &s, &c);
    float a1 = (phi + om) * 0.5f, a2 = (phi - om) * 0.5f;
    float c1, s1, c2, s2;
    sincosf(a1, &s1, &c1);
    sincosf(a2, &s2, &c2);
    float* u = rot + t * 8;
    u[0] =  c * c1;  u[1] = -c * s1;   // U00
    u[2] = -s * c2;  u[3] = -s * s2;   // U01
    u[4] =  s * c2;  u[5] = -s * s2;   // U10
    u[6] =  c * c1;  u[7] =  c * s1;   // U11
}

// out[M][C] = act(in[M][K] @ W[C][K]^T + b). Block: C threads, ROWS rows.
template<int K, int C, int ROWS, bool RELU>
__global__ void gemm_bias_kernel(const float* __restrict__ in,
                                 const float* __restrict__ W,
                                 const float* __restrict__ b,
                                 float* __restrict__ out, int M) {
    extern __shared__ float sm[];
    float* Ws = sm;                    // C * (K+1), padded to kill bank conflicts
    float* Is = sm + C * (K + 1);      // ROWS * K
    int tid = threadIdx.x;
    for (int idx = tid; idx < C * K; idx += C)
        Ws[(idx / K) * (K + 1) + (idx % K)] = W[idx];
    int r0 = blockIdx.x * ROWS;
    int nr = min(ROWS, M - r0);
    for (int idx = tid; idx < nr * K; idx += C)
        Is[idx] = in[r0 * K + idx];
    __syncthreads();
    int c = tid;
    float bias = b[c];
    float acc[ROWS];
#pragma unroll
    for (int r = 0; r < ROWS; r++) acc[r] = bias;
    const float* wr = Ws + c * (K + 1);
#pragma unroll 4
    for (int k = 0; k < K; k++) {
        float w = wr[k];
#pragma unroll
        for (int r = 0; r < ROWS; r++) acc[r] += Is[r * K + k] * w;
    }
    for (int r = 0; r < nr; r++) {
        float v = acc[r];
        if (RELU) v = fmaxf(v, 0.f);
        out[(r0 + r) * C + c] = v;
    }
}

// One warp per node: q/k projections (+tanh), entangle circuit, x_comb update.
__global__ void node_q_kernel(const float* __restrict__ h,
                              float* __restrict__ xc,
                              const float* __restrict__ attqW, const float* __restrict__ attqb,
                              const float* __restrict__ attkW, const float* __restrict__ attkb,
                              const float* __restrict__ qprojW, const float* __restrict__ qprojb,
                              const float* __restrict__ entrot,
                              float* __restrict__ qout, float* __restrict__ kout, int N) {
    int gwid = (blockIdx.x * blockDim.x + threadIdx.x) >> 5;
    int lane = threadIdx.x & 31;
    if (gwid >= N) return;
    const float4 hv = *(const float4*)(h + gwid * 128 + lane * 4);
    float acc[8];
#pragma unroll
    for (int j = 0; j < 8; j++) {
        const float* Wr = (j < 4 ? attqW + j * 128 : attkW + (j - 4) * 128) + lane * 4;
        float4 w = *(const float4*)Wr;
        acc[j] = hv.x * w.x + hv.y * w.y + hv.z * w.z + hv.w * w.w;
    }
#pragma unroll
    for (int off = 16; off; off >>= 1)
#pragma unroll
        for (int j = 0; j < 8; j++)
            acc[j] += __shfl_xor_sync(0xffffffffu, acc[j], off);
    float qv[4], kv[4];
#pragma unroll
    for (int j = 0; j < 4; j++) {
        qv[j] = tanhf(acc[j] + attqb[j]) * PI_HALF;
        kv[j] = tanhf(acc[4 + j] + attkb[j]) * PI_HALF;
    }
    if (lane < 4) {
        qout[gwid * 4 + lane] = qv[lane];
        kout[gwid * 4 + lane] = kv[lane];
    }
    // entangle circuit input = tanh(h[n][0:4]) * pi/2 (lane 0 holds them)
    float xin[4];
    xin[0] = tanhf(__shfl_sync(0xffffffffu, hv.x, 0)) * PI_HALF;
    xin[1] = tanhf(__shfl_sync(0xffffffffu, hv.y, 0)) * PI_HALF;
    xin[2] = tanhf(__shfl_sync(0xffffffffu, hv.z, 0)) * PI_HALF;
    xin[3] = tanhf(__shfl_sync(0xffffffffu, hv.w, 0)) * PI_HALF;
    float z[4];
    entangle_circ(xin, entrot, z);   // all lanes redundantly (SIMT-free)
    // x_comb[c] = x_cls[c] + sum_j z[j]*qprojW[c][j] + qprojb[c], c = lane*4+i
    float4 xcv = *(const float4*)(xc + gwid * 128 + lane * 4);
    float res[4] = {xcv.x, xcv.y, xcv.z, xcv.w};
#pragma unroll
    for (int i = 0; i < 4; i++) {
        int c = lane * 4 + i;
        float4 qp = *(const float4*)(qprojW + c * 4);
        res[i] += z[0] * qp.x + z[1] * qp.y + z[2] * qp.z + z[3] * qp.w + qprojb[c];
    }
    *(float4*)(xc + gwid * 128 + lane * 4) = make_float4(res[0], res[1], res[2], res[3]);
}

// One thread per edge: attention circuit -> exp(score); block-reduced global sum.
__global__ void edge_score_kernel(const float* __restrict__ q,
                                  const float* __restrict__ k,
                                  const int* __restrict__ ei, int E0, int N,
                                  const float* __restrict__ attrot,
                                  float* __restrict__ att, float* __restrict__ sumptr) {
    int e = blockIdx.x * blockDim.x + threadIdx.x;
    int Et = E0 + N;
    float es = 0.f;
    if (e < Et) {
        int s, d;
        if (e < E0) { s = ei[e]; d = ei[E0 + e]; }
        else        { s = d = e - E0; }
        float4 qa = *(const float4*)(q + s * 4);
        float4 ka = *(const float4*)(k + d * 4);
        float qq[4] = {qa.x, qa.y, qa.z, qa.w};
        float kk[4] = {ka.x, ka.y, ka.z, ka.w};
        float score = att_circ(qq, kk, attrot);
        es = expf(score);                 // scores in [-1,1]: no max pass needed
        att[e] = es;
    }
    float v = es;
#pragma unroll
    for (int off = 16; off; off >>= 1) v += __shfl_xor_sync(0xffffffffu, v, off);
    __shared__ float sred[8];
    int lane = threadIdx.x & 31, warp = threadIdx.x >> 5;
    if (lane == 0) sred[warp] = v;
    __syncthreads();
    if (threadIdx.x == 0) {
        float t = 0.f;
#pragma unroll
        for (int i = 0; i < 8; i++) t += sred[i];
        atomicAdd(sumptr, t);
    }
}

// One warp per edge: h_new[dst] += (att[e]/sum) * x_comb[src]  (float4 atomics)
__global__ void edge_scatter_kernel(const float* __restrict__ att,
                                    const float* __restrict__ sumptr,
                                    const float* __restrict__ xc,
                                    const int* __restrict__ ei, int E0, int N,
                                    float* __restrict__ hn) {
    int gw = (blockIdx.x * blockDim.x + threadIdx.x) >> 5;
    int lane = threadIdx.x & 31;
    int Et = E0 + N;
    if (gw >= Et) return;
    int s, d;
    if (gw < E0) { s = ei[gw]; d = ei[E0 + gw]; }
    else         { s = d = gw - E0; }
    float w = att[gw] / sumptr[0];
    const float4* xs = (const float4*)(xc + s * 128);
    float4* hd = (float4*)(hn + d * 128);
    float4 v = xs[lane];
    atomicAdd(hd + lane, make_float4(w * v.x, w * v.y, w * v.z, w * v.w));
}

__global__ void relu_kernel(float* __restrict__ p, int n) {
    int i = blockIdx.x * blockDim.x + threadIdx.x;
    if (i * 4 < n) {
        float4 v = ((float4*)p)[i];
        ((float4*)p)[i] = make_float4(fmaxf(v.x, 0.f), fmaxf(v.y, 0.f),
                                      fmaxf(v.z, 0.f), fmaxf(v.w, 0.f));
    }
}

// One warp per node: pq projection, path circuit, path_out linear, final out linear.
__global__ void path_kernel(const float* __restrict__ h,
                            const float* __restrict__ piW, const float* __restrict__ pib,
                            const float* __restrict__ pathrot,
                            const float* __restrict__ poW, const float* __restrict__ pob,
                            const float* __restrict__ outW, const float* __restrict__ outb,
                            float* __restrict__ out, int N) {
    __shared__ float oW[32 * 129];
    __shared__ float h2[8][128];
    int tid = threadIdx.x;
    for (int idx = tid; idx < 32 * 128; idx += 256)
        oW[(idx >> 7) * 129 + (idx & 127)] = outW[idx];
    __syncthreads();
    int warp = tid >> 5, lane = tid & 31;
    int n = blockIdx.x * 8 + warp;
    if (n < N) {
        float4 hv = *(const float4*)(h + n * 128 + lane * 4);
        float acc[4];
#pragma unroll
        for (int j = 0; j < 4; j++) {
            float4 w = *(const float4*)(piW + j * 128 + lane * 4);
            acc[j] = hv.x * w.x + hv.y * w.y + hv.z * w.z + hv.w * w.w;
        }
#pragma unroll
        for (int off = 16; off; off >>= 1)
#pragma unroll
            for (int j = 0; j < 4; j++)
                acc[j] += __shfl_xor_sync(0xffffffffu, acc[j], off);
        float pq[4];
#pragma unroll
        for (int j = 0; j < 4; j++) pq[j] = tanhf(acc[j] + pib[j]) * PI_HALF;
        float z[4];
        path_circ(pq, pathrot, z);
#pragma unroll
        for (int i = 0; i < 4; i++) {
            int c = lane * 4 + i;
            float4 w = *(const float4*)(poW + c * 4);
            h2[warp][c] = pob[c] + z[0] * w.x + z[1] * w.y + z[2] * w.z + z[3] * w.w;
        }
    }
    __syncwarp();
    if (n < N) {
        float a = outb[lane];
        const float* wr = oW + lane * 129;
#pragma unroll 4
        for (int kk = 0; kk < 128; kk++) a += h2[warp][kk] * wr[kk];
        out[n * 32 + lane] = a;
    }
}

// ---------------- host ----------------
extern "C" void kernel_launch(void* const* d_in, const int* in_sizes, int n_in,
                              void* d_out, int out_size) {
    const float* x        = (const float*)d_in[0];
    const float* W_in     = (const float*)d_in[1];
    const float* b_in     = (const float*)d_in[2];
    const float* lin_W    = (const float*)d_in[3];
    const float* lin_b    = (const float*)d_in[4];
    const float* qproj_W  = (const float*)d_in[5];
    const float* qproj_b  = (const float*)d_in[6];
    const float* ent_p    = (const float*)d_in[7];
    const float* attq_W   = (const float*)d_in[8];
    const float* attq_b   = (const float*)d_in[9];
    const float* attk_W   = (const float*)d_in[10];
    const float* attk_b   = (const float*)d_in[11];
    const float* att_qp   = (const float*)d_in[12];
    const float* path_p   = (const float*)d_in[13];
    const float* pi_W     = (const float*)d_in[14];
    const float* pi_b     = (const float*)d_in[15];
    const float* po_W     = (const float*)d_in[16];
    const float* po_b     = (const float*)d_in[17];
    const float* out_W    = (const float*)d_in[18];
    const float* out_b    = (const float*)d_in[19];
    const int*   ei       = (const int*)d_in[20];
    float* out = (float*)d_out;

    int N  = in_sizes[0] / 64;
    int E0 = in_sizes[20] / 2;
    int Et = E0 + N;

    float *bufA, *bufB, *xc, *qb, *kb, *att, *sum, *rot;
    cudaGetSymbolAddress((void**)&bufA, g_bufA);
    cudaGetSymbolAddress((void**)&bufB, g_bufB);
    cudaGetSymbolAddress((void**)&xc,   g_xc);
    cudaGetSymbolAddress((void**)&qb,   g_q);
    cudaGetSymbolAddress((void**)&kb,   g_k);
    cudaGetSymbolAddress((void**)&att,  g_att);
    cudaGetSymbolAddress((void**)&sum,  g_sum);
    cudaGetSymbolAddress((void**)&rot,  g_rot);

    const int SMEM64  = (128 * 65 + 16 * 64) * 4;    // 37376
    const int SMEM128 = (128 * 129 + 16 * 128) * 4;  // 74240
    cudaFuncSetAttribute(gemm_bias_kernel<64, 128, 16, true>,
                         cudaFuncAttributeMaxDynamicSharedMemorySize, SMEM64);
    cudaFuncSetAttribute(gemm_bias_kernel<128, 128, 16, false>,
                         cudaFuncAttributeMaxDynamicSharedMemorySize, SMEM128);

    prep_kernel<<<1, 64>>>(att_qp, ent_p, path_p, rot, sum);

    // h0 = relu(x @ W_in^T + b_in)
    gemm_bias_kernel<64, 128, 16, true>
        <<<(N + 15) / 16, 128, SMEM64>>>(x, W_in, b_in, bufA, N);

    float* hcur = bufA;
    float* hnext = bufB;
    for (int l = 0; l < 2; l++) {
        // x_cls = h @ lin_W^T + lin_b
        gemm_bias_kernel<128, 128, 16, false>
            <<<(N + 15) / 16, 128, SMEM128>>>(hcur, lin_W + l * 128 * 128,
                                              lin_b + l * 128, xc, N);
        // q, k, xq circuit, x_comb (in place over xc)
        node_q_kernel<<<(N * 32 + 255) / 256, 256>>>(
            hcur, xc,
            attq_W + l * 4 * 128, attq_b + l * 4,
            attk_W + l * 4 * 128, attk_b + l * 4,
            qproj_W + l * 128 * 4, qproj_b + l * 128,
            rot + 64 + l * 64, qb, kb, N);
        cudaMemsetAsync(hnext, 0, (size_t)N * 128 * sizeof(float), 0);
        edge_score_kernel<<<(Et + 255) / 256, 256>>>(
            qb, kb, ei, E0, N, rot + l * 32, att, sum + l);
        edge_scatter_kernel<<<(Et * 32 + 255) / 256, 256>>>(
            att, sum + l, xc, ei, E0, N, hnext);
        relu_kernel<<<(N * 128 / 4 + 255) / 256, 256>>>(hnext, N * 128);
        float* t = hcur; hcur = hnext; hnext = t;
    }

    path_kernel<<<(N + 7) / 8, 256>>>(hcur, pi_W, pi_b, rot + 192,
                                      po_W, po_b, out_W, out_b, out, N);
}

// round 6
// speedup vs baseline: 1.3778x; 1.3778x over previous
#include <cuda_runtime.h>
#include <cuda_bf16.h>

#define PI_HALF 1.57079632679489662f
#define NMAX 20000
#define EMAX 300000

// ---------------- scratch (no allocation allowed) ----------------
__device__ float g_bufA[NMAX * 128];
__device__ float g_bufB[NMAX * 128];
__device__ float g_xc[NMAX * 128];
__device__ float g_q[NMAX * 4];
__device__ float g_k[NMAX * 4];
__device__ float g_z[NMAX * 4];
__device__ float g_att[EMAX + NMAX];
__device__ float g_sum[2];
__device__ float g_rot[36 * 8];          // 36 complex 2x2 matrices
__device__ int   g_deg[NMAX + 1];
__device__ int   g_rowptr[NMAX + 1];
__device__ int   g_cursor[NMAX + 1];
__device__ int   g_csr_src[EMAX + NMAX];
__device__ int   g_csr_eid[EMAX + NMAX];
__device__ float g_M[32 * 4];
__device__ float g_c0[32];

// ---------------- complex helpers ----------------
__device__ __forceinline__ float2 cmul(float2 a, float2 b) {
    return make_float2(a.x * b.x - a.y * b.y, a.x * b.y + a.y * b.x);
}

// Single-qubit gates; M = bit mask of the wire (wire w -> mask 1<<(3-w)).
template<int M>
__device__ __forceinline__ void ap_ry(float2* s, float c, float sn) {
#pragma unroll
    for (int i = 0; i < 16; i++) {
        if (i & M) continue;
        float2 a = s[i], b = s[i | M];
        s[i]     = make_float2(c * a.x - sn * b.x, c * a.y - sn * b.y);
        s[i | M] = make_float2(sn * a.x + c * b.x, sn * a.y + c * b.y);
    }
}

template<int M>
__device__ __forceinline__ void ap_h(float2* s) {
    const float r = 0.70710678118654752f;
#pragma unroll
    for (int i = 0; i < 16; i++) {
        if (i & M) continue;
        float2 a = s[i], b = s[i | M];
        s[i]     = make_float2((a.x + b.x) * r, (a.y + b.y) * r);
        s[i | M] = make_float2((a.x - b.x) * r, (a.y - b.y) * r);
    }
}

template<int MC, int MT>
__device__ __forceinline__ void ap_cry(float2* s, float c, float sn) {
#pragma unroll
    for (int i = 0; i < 16; i++) {
        if (!(i & MC) || (i & MT)) continue;
        float2 a = s[i], b = s[i | MT];
        s[i]      = make_float2(c * a.x - sn * b.x, c * a.y - sn * b.y);
        s[i | MT] = make_float2(sn * a.x + c * b.x, sn * a.y + c * b.y);
    }
}

template<int MC, int MT>
__device__ __forceinline__ void ap_cnot(float2* s) {
#pragma unroll
    for (int i = 0; i < 16; i++) {
        if (!(i & MC) || (i & MT)) continue;
        float2 t = s[i];
        s[i] = s[i | MT];
        s[i | MT] = t;
    }
}

template<int M>
__device__ __forceinline__ void ap_rot(float2* s, const float* __restrict__ u) {
    float2 u00 = make_float2(u[0], u[1]);
    float2 u01 = make_float2(u[2], u[3]);
    float2 u10 = make_float2(u[4], u[5]);
    float2 u11 = make_float2(u[6], u[7]);
#pragma unroll
    for (int i = 0; i < 16; i++) {
        if (i & M) continue;
        float2 a = s[i], b = s[i | M];
        float2 ra = cmul(u00, a), rb = cmul(u01, b);
        float2 sa = cmul(u10, a), sb = cmul(u11, b);
        s[i]     = make_float2(ra.x + rb.x, ra.y + rb.y);
        s[i | M] = make_float2(sa.x + sb.x, sa.y + sb.y);
    }
}

__device__ __forceinline__ void init_state(float2* s) {
#pragma unroll
    for (int i = 0; i < 16; i++) s[i] = make_float2(0.f, 0.f);
    s[0] = make_float2(1.f, 0.f);
}

__device__ __forceinline__ void zexp4(const float2* s, float z[4]) {
    z[0] = z[1] = z[2] = z[3] = 0.f;
#pragma unroll
    for (int i = 0; i < 16; i++) {
        float n = s[i].x * s[i].x + s[i].y * s[i].y;
        z[0] += (i & 8) ? -n : n;
        z[1] += (i & 4) ? -n : n;
        z[2] += (i & 2) ? -n : n;
        z[3] += (i & 1) ? -n : n;
    }
}

__device__ __forceinline__ void ry_all(float2* s, const float a[4]) {
    float c, sn;
    __sincosf(a[0] * 0.5f, &sn, &c); ap_ry<8>(s, c, sn);
    __sincosf(a[1] * 0.5f, &sn, &c); ap_ry<4>(s, c, sn);
    __sincosf(a[2] * 0.5f, &sn, &c); ap_ry<2>(s, c, sn);
    __sincosf(a[3] * 0.5f, &sn, &c); ap_ry<1>(s, c, sn);
}

__device__ __forceinline__ void rot_all(float2* s, const float* __restrict__ rm) {
    ap_rot<8>(s, rm);
    ap_rot<4>(s, rm + 8);
    ap_rot<2>(s, rm + 16);
    ap_rot<1>(s, rm + 24);
}

// ---------------- circuits ----------------
__device__ __forceinline__ void entangle_circ(const float xin[4],
                                              const float* __restrict__ rot,
                                              float z[4]) {
    float2 s[16];
    init_state(s);
    ry_all(s, xin);
#pragma unroll
    for (int l = 0; l < 2; l++) {
        ap_cnot<8, 4>(s); ap_cnot<4, 2>(s); ap_cnot<2, 1>(s);
        rot_all(s, rot + l * 32);
        ap_cnot<8, 1>(s);
    }
    zexp4(s, z);
}

__device__ __forceinline__ float att_circ(const float q[4], const float k[4],
                                          const float* __restrict__ rot) {
    float2 s[16];
    init_state(s);
    ry_all(s, q);
    ap_h<8>(s); ap_h<4>(s); ap_h<2>(s); ap_h<1>(s);
    float c, sn;
    __sincosf(k[0] * 0.5f, &sn, &c); ap_cry<8, 4>(s, c, sn);
    __sincosf(k[1] * 0.5f, &sn, &c); ap_cry<4, 2>(s, c, sn);
    __sincosf(k[2] * 0.5f, &sn, &c); ap_cry<2, 1>(s, c, sn);
    __sincosf(k[3] * 0.5f, &sn, &c); ap_cry<1, 8>(s, c, sn);
    rot_all(s, rot);
    float score = 0.f;
#pragma unroll
    for (int i = 0; i < 16; i++) {
        float n = s[i].x * s[i].x + s[i].y * s[i].y;
        score += n * (1.0f - 0.5f * (float)__popc(i));   // mean of 4 Z exps
    }
    return score;
}

__device__ __forceinline__ void path_circ(const float xin[4],
                                          const float* __restrict__ rot,
                                          float z[4]) {
    float2 s[16];
    init_state(s);
    ap_h<8>(s); ap_h<4>(s); ap_h<2>(s); ap_h<1>(s);
    ry_all(s, xin);
#pragma unroll
    for (int l = 0; l < 3; l++) {
        rot_all(s, rot + l * 32);
        ap_cnot<8, 4>(s); ap_cnot<4, 2>(s); ap_cnot<2, 1>(s);
    }
    zexp4(s, z);
}

// ---------------- kernels ----------------

// Precompute all 36 Rot matrices + zero softmax accumulators.
__global__ void prep_kernel(const float* __restrict__ attqp,
                            const float* __restrict__ entp,
                            const float* __restrict__ pathp,
                            float* __restrict__ rot, float* __restrict__ sums) {
    int t = threadIdx.x;
    if (t < 2) sums[t] = 0.f;
    if (t >= 36) return;
    const float* p;
    if (t < 8)       p = attqp + t * 3;
    else if (t < 24) p = entp + (t - 8) * 3;
    else             p = pathp + (t - 24) * 3;
    float phi = p[0], th = p[1], om = p[2];
    float c, s;  sincosf(th * 0.5f, &s, &c);
    float a1 = (phi + om) * 0.5f, a2 = (phi - om) * 0.5f;
    float c1, s1, c2, s2;
    sincosf(a1, &s1, &c1);
    sincosf(a2, &s2, &c2);
    float* u = rot + t * 8;
    u[0] =  c * c1;  u[1] = -c * s1;
    u[2] = -s * c2;  u[3] = -s * s2;
    u[4] =  s * c2;  u[5] = -s * s2;
    u[6] =  c * c1;  u[7] =  c * s1;
}

// Collapse path epilogue: M = outW @ poW [32x4], c0 = outb + outW @ pob [32]
__global__ void path_precomp_kernel(const float* __restrict__ poW,
                                    const float* __restrict__ pob,
                                    const float* __restrict__ outW,
                                    const float* __restrict__ outb,
                                    float* __restrict__ M, float* __restrict__ c0) {
    int o = threadIdx.x >> 2, j = threadIdx.x & 3;
    float m = 0.f;
    for (int k = 0; k < 128; k++) m += outW[o * 128 + k] * poW[k * 4 + j];
    M[o * 4 + j] = m;
    if (j == 0) {
        float cc = outb[o];
        for (int k = 0; k < 128; k++) cc += outW[o * 128 + k] * pob[k];
        c0[o] = cc;
    }
}

// ---- CSR build (once per launch; edge set is constant across layers) ----
__global__ void csr_count_kernel(const int* __restrict__ ei, int E0, int N,
                                 int* __restrict__ cnt) {
    int e = blockIdx.x * blockDim.x + threadIdx.x;
    if (e >= E0 + N) return;
    int d = (e < E0) ? ei[E0 + e] : e - E0;
    atomicAdd(&cnt[d], 1);
}

__global__ void csr_scan_kernel(const int* __restrict__ cnt,
                                int* __restrict__ rowptr, int* __restrict__ cursor,
                                int N) {
    __shared__ int sh[1024];
    __shared__ int carry;
    int tid = threadIdx.x;
    if (tid == 0) carry = 0;
    __syncthreads();
    for (int base = 0; base < N; base += 1024) {
        int i = base + tid;
        int v = (i < N) ? cnt[i] : 0;
        sh[tid] = v;
        __syncthreads();
#pragma unroll
        for (int off = 1; off < 1024; off <<= 1) {
            int t = (tid >= off) ? sh[tid - off] : 0;
            __syncthreads();
            sh[tid] += t;
            __syncthreads();
        }
        int excl = carry + sh[tid] - v;
        if (i < N) { rowptr[i] = excl; cursor[i] = excl; }
        __syncthreads();
        if (tid == 1023) carry += sh[1023];
        __syncthreads();
    }
    if (tid == 0) { rowptr[N] = carry; cursor[N] = carry; }
}

__global__ void csr_fill_kernel(const int* __restrict__ ei, int E0, int N,
                                int* __restrict__ cursor,
                                int* __restrict__ csr_src, int* __restrict__ csr_eid) {
    int e = blockIdx.x * blockDim.x + threadIdx.x;
    if (e >= E0 + N) return;
    int s, d;
    if (e < E0) { s = ei[e]; d = ei[E0 + e]; }
    else        { s = d = e - E0; }
    int p = atomicAdd(&cursor[d], 1);
    csr_src[p] = s;
    csr_eid[p] = e;
}

// out[M][C] = act(in[M][K] @ W[C][K]^T + b). C threads per block, float4 inner loop.
template<int K, int C, int ROWS, bool RELU>
__global__ void gemm_bias_kernel(const float* __restrict__ in,
                                 const float* __restrict__ W,
                                 const float* __restrict__ b,
                                 float* __restrict__ out, int M) {
    extern __shared__ float sm[];
    float* Ws = sm;                    // C * (K+4)  (pad keeps float4 rows conflict-free)
    float* Is = sm + C * (K + 4);      // ROWS * K
    int tid = threadIdx.x;
    for (int idx = tid; idx < C * K; idx += C)
        Ws[(idx / K) * (K + 4) + (idx % K)] = W[idx];
    int r0 = blockIdx.x * ROWS;
    int nr = min(ROWS, M - r0);
    for (int idx = tid; idx < nr * K; idx += C)
        Is[idx] = in[r0 * K + idx];
    __syncthreads();
    int c = tid;
    float acc[ROWS];
#pragma unroll
    for (int r = 0; r < ROWS; r++) acc[r] = 0.f;
    const float4* wr = (const float4*)(Ws + c * (K + 4));
#pragma unroll 2
    for (int k4 = 0; k4 < K / 4; k4++) {
        float4 w = wr[k4];
#pragma unroll
        for (int r = 0; r < ROWS; r++) {
            float4 iv = *(const float4*)(Is + r * K + k4 * 4);
            acc[r] += iv.x * w.x + iv.y * w.y + iv.z * w.z + iv.w * w.w;
        }
    }
    float bias = b[c];
    for (int r = 0; r < nr; r++) {
        float v = acc[r] + bias;
        if (RELU) v = fmaxf(v, 0.f);
        out[(r0 + r) * C + c] = v;
    }
}

// Thread per node: entangle circuit only (no 32x lane redundancy).
__global__ void ent_kernel(const float* __restrict__ h,
                           const float* __restrict__ entrot,
                           float* __restrict__ z, int N) {
    int n = blockIdx.x * blockDim.x + threadIdx.x;
    if (n >= N) return;
    float4 hv = *(const float4*)(h + n * 128);
    float xin[4] = {tanhf(hv.x) * PI_HALF, tanhf(hv.y) * PI_HALF,
                    tanhf(hv.z) * PI_HALF, tanhf(hv.w) * PI_HALF};
    float zz[4];
    entangle_circ(xin, entrot, zz);
    *(float4*)(z + n * 4) = make_float4(zz[0], zz[1], zz[2], zz[3]);
}

// Warp per node: q/k projections (+tanh) and x_comb update using precomputed z.
__global__ void node_proj_kernel(const float* __restrict__ h,
                                 float* __restrict__ xc,
                                 const float* __restrict__ attqW, const float* __restrict__ attqb,
                                 const float* __restrict__ attkW, const float* __restrict__ attkb,
                                 const float* __restrict__ qprojW, const float* __restrict__ qprojb,
                                 const float* __restrict__ z,
                                 float* __restrict__ qout, float* __restrict__ kout, int N) {
    int gwid = (blockIdx.x * blockDim.x + threadIdx.x) >> 5;
    int lane = threadIdx.x & 31;
    if (gwid >= N) return;
    const float4 hv = *(const float4*)(h + gwid * 128 + lane * 4);
    float acc[8];
#pragma unroll
    for (int j = 0; j < 8; j++) {
        const float* Wr = (j < 4 ? attqW + j * 128 : attkW + (j - 4) * 128) + lane * 4;
        float4 w = *(const float4*)Wr;
        acc[j] = hv.x * w.x + hv.y * w.y + hv.z * w.z + hv.w * w.w;
    }
#pragma unroll
    for (int off = 16; off; off >>= 1)
#pragma unroll
        for (int j = 0; j < 8; j++)
            acc[j] += __shfl_xor_sync(0xffffffffu, acc[j], off);
    if (lane < 4) {
        qout[gwid * 4 + lane] = tanhf(acc[lane] + attqb[lane]) * PI_HALF;
        kout[gwid * 4 + lane] = tanhf(acc[4 + lane] + attkb[lane]) * PI_HALF;
    }
    float4 zv = *(const float4*)(z + gwid * 4);
    float4 xcv = *(const float4*)(xc + gwid * 128 + lane * 4);
    float res[4] = {xcv.x, xcv.y, xcv.z, xcv.w};
#pragma unroll
    for (int i = 0; i < 4; i++) {
        int c = lane * 4 + i;
        float4 qp = *(const float4*)(qprojW + c * 4);
        res[i] += zv.x * qp.x + zv.y * qp.y + zv.z * qp.z + zv.w * qp.w + qprojb[c];
    }
    *(float4*)(xc + gwid * 128 + lane * 4) = make_float4(res[0], res[1], res[2], res[3]);
}

// One thread per edge: attention circuit -> exp(score); block-reduced global sum.
__global__ void edge_score_kernel(const float* __restrict__ q,
                                  const float* __restrict__ k,
                                  const int* __restrict__ ei, int E0, int N,
                                  const float* __restrict__ attrot,
                                  float* __restrict__ att, float* __restrict__ sumptr) {
    int e = blockIdx.x * blockDim.x + threadIdx.x;
    int Et = E0 + N;
    float es = 0.f;
    if (e < Et) {
        int s, d;
        if (e < E0) { s = ei[e]; d = ei[E0 + e]; }
        else        { s = d = e - E0; }
        float4 qa = *(const float4*)(q + s * 4);
        float4 ka = *(const float4*)(k + d * 4);
        float qq[4] = {qa.x, qa.y, qa.z, qa.w};
        float kk[4] = {ka.x, ka.y, ka.z, ka.w};
        float score = att_circ(qq, kk, attrot);
        es = expf(score);                 // scores in [-1,1]: no max pass needed
        att[e] = es;
    }
    float v = es;
#pragma unroll
    for (int off = 16; off; off >>= 1) v += __shfl_xor_sync(0xffffffffu, v, off);
    __shared__ float sred[8];
    int lane = threadIdx.x & 31, warp = threadIdx.x >> 5;
    if (lane == 0) sred[warp] = v;
    __syncthreads();
    if (threadIdx.x == 0) {
        float t = 0.f;
#pragma unroll
        for (int i = 0; i < 8; i++) t += sred[i];
        atomicAdd(sumptr, t);
    }
}

// Warp per node: atomic-free CSR gather + fused ReLU (replaces memset+scatter+relu).
__global__ void aggregate_kernel(const float* __restrict__ att,
                                 const float* __restrict__ sumptr,
                                 const float* __restrict__ xc,
                                 const int* __restrict__ rowptr,
                                 const int* __restrict__ csr_src,
                                 const int* __restrict__ csr_eid,
                                 float* __restrict__ hn, int N) {
    int n = (blockIdx.x * blockDim.x + threadIdx.x) >> 5;
    int lane = threadIdx.x & 31;
    if (n >= N) return;
    float inv = 1.0f / sumptr[0];
    int beg = rowptr[n], end = rowptr[n + 1];
    float4 acc = make_float4(0.f, 0.f, 0.f, 0.f);
#pragma unroll 2
    for (int i = beg; i < end; i++) {
        int s = csr_src[i];
        float w = att[csr_eid[i]] * inv;
        float4 v = *(const float4*)(xc + s * 128 + lane * 4);
        acc.x += w * v.x; acc.y += w * v.y; acc.z += w * v.z; acc.w += w * v.w;
    }
    acc.x = fmaxf(acc.x, 0.f); acc.y = fmaxf(acc.y, 0.f);
    acc.z = fmaxf(acc.z, 0.f); acc.w = fmaxf(acc.w, 0.f);
    *(float4*)(hn + n * 128 + lane * 4) = acc;
}

// Warp per node: pq projection only.
__global__ void path_proj_kernel(const float* __restrict__ h,
                                 const float* __restrict__ piW, const float* __restrict__ pib,
                                 float* __restrict__ pq, int N) {
    int n = (blockIdx.x * blockDim.x + threadIdx.x) >> 5;
    int lane = threadIdx.x & 31;
    if (n >= N) return;
    float4 hv = *(const float4*)(h + n * 128 + lane * 4);
    float acc[4];
#pragma unroll
    for (int j = 0; j < 4; j++) {
        float4 w = *(const float4*)(piW + j * 128 + lane * 4);
        acc[j] = hv.x * w.x + hv.y * w.y + hv.z * w.z + hv.w * w.w;
    }
#pragma unroll
    for (int off = 16; off; off >>= 1)
#pragma unroll
        for (int j = 0; j < 4; j++)
            acc[j] += __shfl_xor_sync(0xffffffffu, acc[j], off);
    if (lane < 4)
        pq[n * 4 + lane] = tanhf(acc[lane] + pib[lane]) * PI_HALF;
}

// Thread per node: path circuit + collapsed epilogue out = c0 + M @ z.
__global__ void path_out_kernel(const float* __restrict__ pq,
                                const float* __restrict__ pathrot,
                                const float* __restrict__ M, const float* __restrict__ c0,
                                float* __restrict__ out, int N) {
    int n = blockIdx.x * blockDim.x + threadIdx.x;
    if (n >= N) return;
    float4 p = *(const float4*)(pq + n * 4);
    float xin[4] = {p.x, p.y, p.z, p.w};
    float z[4];
    path_circ(xin, pathrot, z);
    float4* o4 = (float4*)(out + n * 32);
#pragma unroll
    for (int g = 0; g < 8; g++) {
        float4 r;
        float* rp = (float*)&r;
#pragma unroll
        for (int i = 0; i < 4; i++) {
            int o = g * 4 + i;
            float4 m = *(const float4*)(M + o * 4);
            rp[i] = c0[o] + z[0] * m.x + z[1] * m.y + z[2] * m.z + z[3] * m.w;
        }
        o4[g] = r;
    }
}

// ---------------- host ----------------
extern "C" void kernel_launch(void* const* d_in, const int* in_sizes, int n_in,
                              void* d_out, int out_size) {
    const float* x        = (const float*)d_in[0];
    const float* W_in     = (const float*)d_in[1];
    const float* b_in     = (const float*)d_in[2];
    const float* lin_W    = (const float*)d_in[3];
    const float* lin_b    = (const float*)d_in[4];
    const float* qproj_W  = (const float*)d_in[5];
    const float* qproj_b  = (const float*)d_in[6];
    const float* ent_p    = (const float*)d_in[7];
    const float* attq_W   = (const float*)d_in[8];
    const float* attq_b   = (const float*)d_in[9];
    const float* attk_W   = (const float*)d_in[10];
    const float* attk_b   = (const float*)d_in[11];
    const float* att_qp   = (const float*)d_in[12];
    const float* path_p   = (const float*)d_in[13];
    const float* pi_W     = (const float*)d_in[14];
    const float* pi_b     = (const float*)d_in[15];
    const float* po_W     = (const float*)d_in[16];
    const float* po_b     = (const float*)d_in[17];
    const float* out_W    = (const float*)d_in[18];
    const float* out_b    = (const float*)d_in[19];
    const int*   ei       = (const int*)d_in[20];
    float* out = (float*)d_out;

    int N  = in_sizes[0] / 64;
    int E0 = in_sizes[20] / 2;
    int Et = E0 + N;

    float *bufA, *bufB, *xc, *qb, *kb, *zb, *att, *sum, *rot, *Mp, *c0p;
    int *deg, *rowptr, *cursor, *csrs, *csre;
    cudaGetSymbolAddress((void**)&bufA,   g_bufA);
    cudaGetSymbolAddress((void**)&bufB,   g_bufB);
    cudaGetSymbolAddress((void**)&xc,     g_xc);
    cudaGetSymbolAddress((void**)&qb,     g_q);
    cudaGetSymbolAddress((void**)&kb,     g_k);
    cudaGetSymbolAddress((void**)&zb,     g_z);
    cudaGetSymbolAddress((void**)&att,    g_att);
    cudaGetSymbolAddress((void**)&sum,    g_sum);
    cudaGetSymbolAddress((void**)&rot,    g_rot);
    cudaGetSymbolAddress((void**)&deg,    g_deg);
    cudaGetSymbolAddress((void**)&rowptr, g_rowptr);
    cudaGetSymbolAddress((void**)&cursor, g_cursor);
    cudaGetSymbolAddress((void**)&csrs,   g_csr_src);
    cudaGetSymbolAddress((void**)&csre,   g_csr_eid);
    cudaGetSymbolAddress((void**)&Mp,     g_M);
    cudaGetSymbolAddress((void**)&c0p,    g_c0);

    const int SMEM64  = (128 * 68 + 16 * 64) * 4;     // 38912
    const int SMEM128 = (128 * 132 + 16 * 128) * 4;   // 75776
    cudaFuncSetAttribute(gemm_bias_kernel<64, 128, 16, true>,
                         cudaFuncAttributeMaxDynamicSharedMemorySize, SMEM64);
    cudaFuncSetAttribute(gemm_bias_kernel<128, 128, 16, false>,
                         cudaFuncAttributeMaxDynamicSharedMemorySize, SMEM128);

    prep_kernel<<<1, 64>>>(att_qp, ent_p, path_p, rot, sum);
    path_precomp_kernel<<<1, 128>>>(po_W, po_b, out_W, out_b, Mp, c0p);

    // CSR by dst (edge set constant across layers; build once)
    cudaMemsetAsync(deg, 0, (size_t)(N + 1) * sizeof(int), 0);
    csr_count_kernel<<<(Et + 255) / 256, 256>>>(ei, E0, N, deg);
    csr_scan_kernel<<<1, 1024>>>(deg, rowptr, cursor, N);
    csr_fill_kernel<<<(Et + 255) / 256, 256>>>(ei, E0, N, cursor, csrs, csre);

    // h0 = relu(x @ W_in^T + b_in)
    gemm_bias_kernel<64, 128, 16, true>
        <<<(N + 15) / 16, 128, SMEM64>>>(x, W_in, b_in, bufA, N);

    float* hcur = bufA;
    float* hnext = bufB;
    for (int l = 0; l < 2; l++) {
        gemm_bias_kernel<128, 128, 16, false>
            <<<(N + 15) / 16, 128, SMEM128>>>(hcur, lin_W + l * 128 * 128,
                                              lin_b + l * 128, xc, N);
        ent_kernel<<<(N + 127) / 128, 128>>>(hcur, rot + 64 + l * 64, zb, N);
        node_proj_kernel<<<(N * 32 + 255) / 256, 256>>>(
            hcur, xc,
            attq_W + l * 4 * 128, attq_b + l * 4,
            attk_W + l * 4 * 128, attk_b + l * 4,
            qproj_W + l * 128 * 4, qproj_b + l * 128,
            zb, qb, kb, N);
        edge_score_kernel<<<(Et + 255) / 256, 256>>>(
            qb, kb, ei, E0, N, rot + l * 32, att, sum + l);
        aggregate_kernel<<<(N * 32 + 255) / 256, 256>>>(
            att, sum + l, xc, rowptr, csrs, csre, hnext, N);
        float* t = hcur; hcur = hnext; hnext = t;
    }

    path_proj_kernel<<<(N * 32 + 255) / 256, 256>>>(hcur, pi_W, pi_b, qb, N);
    path_out_kernel<<<(N + 127) / 128, 128>>>(qb, rot + 192, Mp, c0p, out, N);
}

// round 7
// speedup vs baseline: 1.6648x; 1.2083x over previous
#include <cuda_runtime.h>
#include <cuda_bf16.h>

#define PI_HALF 1.57079632679489662f
#define NMAX 20000
#define EMAX 300000

// ---------------- scratch (no allocation allowed) ----------------
__device__ float g_bufA[NMAX * 128];
__device__ float g_bufB[NMAX * 128];
__device__ float g_xc[NMAX * 128];
__device__ float g_q[NMAX * 4];
__device__ float g_k[NMAX * 4];
__device__ float g_z[NMAX * 4];
__device__ float g_psi[NMAX * 32];       // per-node state after RY(q)+H (16 complex)
__device__ float g_kcs[NMAX * 8];        // per-node cos/sin of k[i]/2
__device__ float g_att[EMAX + NMAX];
__device__ float g_sum[2];
__device__ float g_rot[36 * 8];          // 36 complex 2x2 matrices
__device__ int   g_deg[NMAX + 1];
__device__ int   g_rowptr[NMAX + 1];
__device__ int   g_cursor[NMAX + 1];
__device__ int   g_csr_src[EMAX + NMAX];
__device__ int   g_csr_dst[EMAX + NMAX];
__device__ float g_M[32 * 4];
__device__ float g_c0[32];
__device__ float g_Wt0[64 * 128];        // W_in^T  [K=64][C=128]
__device__ float g_Wt1[2 * 128 * 128];   // lin_W^T [K=128][C=128] per layer

// ---------------- complex helpers ----------------
__device__ __forceinline__ float2 cmul(float2 a, float2 b) {
    return make_float2(a.x * b.x - a.y * b.y, a.x * b.y + a.y * b.x);
}

template<int M>
__device__ __forceinline__ void ap_ry(float2* s, float c, float sn) {
#pragma unroll
    for (int i = 0; i < 16; i++) {
        if (i & M) continue;
        float2 a = s[i], b = s[i | M];
        s[i]     = make_float2(c * a.x - sn * b.x, c * a.y - sn * b.y);
        s[i | M] = make_float2(sn * a.x + c * b.x, sn * a.y + c * b.y);
    }
}

template<int M>
__device__ __forceinline__ void ap_h(float2* s) {
    const float r = 0.70710678118654752f;
#pragma unroll
    for (int i = 0; i < 16; i++) {
        if (i & M) continue;
        float2 a = s[i], b = s[i | M];
        s[i]     = make_float2((a.x + b.x) * r, (a.y + b.y) * r);
        s[i | M] = make_float2((a.x - b.x) * r, (a.y - b.y) * r);
    }
}

template<int MC, int MT>
__device__ __forceinline__ void ap_cry(float2* s, float c, float sn) {
#pragma unroll
    for (int i = 0; i < 16; i++) {
        if (!(i & MC) || (i & MT)) continue;
        float2 a = s[i], b = s[i | MT];
        s[i]      = make_float2(c * a.x - sn * b.x, c * a.y - sn * b.y);
        s[i | MT] = make_float2(sn * a.x + c * b.x, sn * a.y + c * b.y);
    }
}

template<int MC, int MT>
__device__ __forceinline__ void ap_cnot(float2* s) {
#pragma unroll
    for (int i = 0; i < 16; i++) {
        if (!(i & MC) || (i & MT)) continue;
        float2 t = s[i];
        s[i] = s[i | MT];
        s[i | MT] = t;
    }
}

template<int M>
__device__ __forceinline__ void ap_rot(float2* s, const float* __restrict__ u) {
    float2 u00 = make_float2(u[0], u[1]);
    float2 u01 = make_float2(u[2], u[3]);
    float2 u10 = make_float2(u[4], u[5]);
    float2 u11 = make_float2(u[6], u[7]);
#pragma unroll
    for (int i = 0; i < 16; i++) {
        if (i & M) continue;
        float2 a = s[i], b = s[i | M];
        float2 ra = cmul(u00, a), rb = cmul(u01, b);
        float2 sa = cmul(u10, a), sb = cmul(u11, b);
        s[i]     = make_float2(ra.x + rb.x, ra.y + rb.y);
        s[i | M] = make_float2(sa.x + sb.x, sa.y + sb.y);
    }
}

__device__ __forceinline__ void init_state(float2* s) {
#pragma unroll
    for (int i = 0; i < 16; i++) s[i] = make_float2(0.f, 0.f);
    s[0] = make_float2(1.f, 0.f);
}

__device__ __forceinline__ void zexp4(const float2* s, float z[4]) {
    z[0] = z[1] = z[2] = z[3] = 0.f;
#pragma unroll
    for (int i = 0; i < 16; i++) {
        float n = s[i].x * s[i].x + s[i].y * s[i].y;
        z[0] += (i & 8) ? -n : n;
        z[1] += (i & 4) ? -n : n;
        z[2] += (i & 2) ? -n : n;
        z[3] += (i & 1) ? -n : n;
    }
}

__device__ __forceinline__ void ry_all(float2* s, const float a[4]) {
    float c, sn;
    __sincosf(a[0] * 0.5f, &sn, &c); ap_ry<8>(s, c, sn);
    __sincosf(a[1] * 0.5f, &sn, &c); ap_ry<4>(s, c, sn);
    __sincosf(a[2] * 0.5f, &sn, &c); ap_ry<2>(s, c, sn);
    __sincosf(a[3] * 0.5f, &sn, &c); ap_ry<1>(s, c, sn);
}

__device__ __forceinline__ void rot_all(float2* s, const float* __restrict__ rm) {
    ap_rot<8>(s, rm);
    ap_rot<4>(s, rm + 8);
    ap_rot<2>(s, rm + 16);
    ap_rot<1>(s, rm + 24);
}

// ---------------- circuits ----------------
__device__ __forceinline__ void entangle_circ(const float xin[4],
                                              const float* __restrict__ rot,
                                              float z[4]) {
    float2 s[16];
    init_state(s);
    ry_all(s, xin);
#pragma unroll
    for (int l = 0; l < 2; l++) {
        ap_cnot<8, 4>(s); ap_cnot<4, 2>(s); ap_cnot<2, 1>(s);
        rot_all(s, rot + l * 32);
        ap_cnot<8, 1>(s);
    }
    zexp4(s, z);
}

__device__ __forceinline__ void path_circ(const float xin[4],
                                          const float* __restrict__ rot,
                                          float z[4]) {
    float2 s[16];
    init_state(s);
    ap_h<8>(s); ap_h<4>(s); ap_h<2>(s); ap_h<1>(s);
    ry_all(s, xin);
#pragma unroll
    for (int l = 0; l < 3; l++) {
        rot_all(s, rot + l * 32);
        ap_cnot<8, 4>(s); ap_cnot<4, 2>(s); ap_cnot<2, 1>(s);
    }
    zexp4(s, z);
}

// ---------------- small prep kernels ----------------
__global__ void prep_kernel(const float* __restrict__ attqp,
                            const float* __restrict__ entp,
                            const float* __restrict__ pathp,
                            float* __restrict__ rot, float* __restrict__ sums) {
    int t = threadIdx.x;
    if (t < 2) sums[t] = 0.f;
    if (t >= 36) return;
    const float* p;
    if (t < 8)       p = attqp + t * 3;
    else if (t < 24) p = entp + (t - 8) * 3;
    else             p = pathp + (t - 24) * 3;
    float phi = p[0], th = p[1], om = p[2];
    float c, s;  sincosf(th * 0.5f, &s, &c);
    float a1 = (phi + om) * 0.5f, a2 = (phi - om) * 0.5f;
    float c1, s1, c2, s2;
    sincosf(a1, &s1, &c1);
    sincosf(a2, &s2, &c2);
    float* u = rot + t * 8;
    u[0] =  c * c1;  u[1] = -c * s1;
    u[2] = -s * c2;  u[3] = -s * s2;
    u[4] =  s * c2;  u[5] = -s * s2;
    u[6] =  c * c1;  u[7] =  c * s1;
}

__global__ void path_precomp_kernel(const float* __restrict__ poW,
                                    const float* __restrict__ pob,
                                    const float* __restrict__ outW,
                                    const float* __restrict__ outb,
                                    float* __restrict__ M, float* __restrict__ c0) {
    int o = threadIdx.x >> 2, j = threadIdx.x & 3;
    float m = 0.f;
    for (int k = 0; k < 128; k++) m += outW[o * 128 + k] * poW[k * 4 + j];
    M[o * 4 + j] = m;
    if (j == 0) {
        float cc = outb[o];
        for (int k = 0; k < 128; k++) cc += outW[o * 128 + k] * pob[k];
        c0[o] = cc;
    }
}

// W[C][K] -> Wt[K][C]
__global__ void transpose_kernel(const float* __restrict__ W, float* __restrict__ Wt,
                                 int C, int K) {
    int i = blockIdx.x * 256 + threadIdx.x;
    if (i >= C * K) return;
    int c = i / K, k = i % K;
    Wt[k * C + c] = W[i];
}

// ---- CSR build (once per launch) ----
__global__ void csr_count_kernel(const int* __restrict__ ei, int E0, int N,
                                 int* __restrict__ cnt) {
    int e = blockIdx.x * blockDim.x + threadIdx.x;
    if (e >= E0 + N) return;
    int d = (e < E0) ? ei[E0 + e] : e - E0;
    atomicAdd(&cnt[d], 1);
}

// 1024 threads, each owns 20 contiguous elems; shuffle warp scan + block scan.
__global__ void csr_scan_kernel(const int* __restrict__ cnt,
                                int* __restrict__ rowptr, int* __restrict__ cursor,
                                int N) {
    const int IT = (NMAX + 1023) / 1024;   // 20
    __shared__ int wsum[32];
    int tid = threadIdx.x, lane = tid & 31, wid = tid >> 5;
    int base = tid * IT;
    int v[IT];
    int run = 0;
#pragma unroll
    for (int j = 0; j < IT; j++) {
        v[j] = run;
        int i = base + j;
        run += (i < N) ? cnt[i] : 0;
    }
    int s = run;
#pragma unroll
    for (int off = 1; off < 32; off <<= 1) {
        int t = __shfl_up_sync(0xffffffffu, s, off);
        if (lane >= off) s += t;
    }
    if (lane == 31) wsum[wid] = s;
    __syncthreads();
    if (wid == 0) {
        int w = wsum[lane];
        int ws = w;
#pragma unroll
        for (int off = 1; off < 32; off <<= 1) {
            int t = __shfl_up_sync(0xffffffffu, ws, off);
            if (lane >= off) ws += t;
        }
        wsum[lane] = ws - w;   // exclusive
    }
    __syncthreads();
    int offset = wsum[wid] + (s - run);
#pragma unroll
    for (int j = 0; j < IT; j++) {
        int i = base + j;
        if (i <= N) {
            int val = offset + v[j];
            rowptr[i] = val;
            cursor[i] = val;
        }
    }
}

__global__ void csr_fill_kernel(const int* __restrict__ ei, int E0, int N,
                                int* __restrict__ cursor,
                                int* __restrict__ csr_src, int* __restrict__ csr_dst) {
    int e = blockIdx.x * blockDim.x + threadIdx.x;
    if (e >= E0 + N) return;
    int s, d;
    if (e < E0) { s = ei[e]; d = ei[E0 + e]; }
    else        { s = d = e - E0; }
    int p = atomicAdd(&cursor[d], 1);
    csr_src[p] = s;
    csr_dst[p] = d;
}

// ---------------- register-tiled GEMM ----------------
// out[M][128] = act(in[M][K] @ W^T + b), W pre-transposed to Wt[K][128].
// 64x64 tile per block, 256 threads, 4x4 micro-tile.
template<int K, bool RELU>
__global__ void gemm_tile_kernel(const float* __restrict__ in,
                                 const float* __restrict__ Wt,
                                 const float* __restrict__ b,
                                 float* __restrict__ out, int M) {
    extern __shared__ float sm[];
    float* As = sm;             // [64][K] row-major
    float* Bs = sm + 64 * K;    // [K][68]
    int tid = threadIdx.x;
    int r0 = blockIdx.x * 64;
    int c0 = blockIdx.y * 64;
    int nrows = min(64, M - r0);
    for (int idx = tid * 4; idx < 64 * K; idx += 1024) {
        int r = idx / K, k = idx % K;
        float4 v = make_float4(0.f, 0.f, 0.f, 0.f);
        if (r < nrows) v = *(const float4*)(in + (size_t)(r0 + r) * K + k);
        *(float4*)(As + r * K + k) = v;
    }
    for (int idx = tid * 4; idx < K * 64; idx += 1024) {
        int k = idx >> 6, c = idx & 63;
        float4 v = *(const float4*)(Wt + (size_t)k * 128 + c0 + c);
        *(float4*)(Bs + k * 68 + c) = v;
    }
    __syncthreads();
    int tr = (tid >> 4) * 4;
    int tc = (tid & 15) * 4;
    float acc[4][4];
#pragma unroll
    for (int i = 0; i < 4; i++)
#pragma unroll
        for (int j = 0; j < 4; j++) acc[i][j] = 0.f;
#pragma unroll 2
    for (int k = 0; k < K; k += 4) {
        float4 b0 = *(const float4*)(Bs + (k + 0) * 68 + tc);
        float4 b1 = *(const float4*)(Bs + (k + 1) * 68 + tc);
        float4 b2 = *(const float4*)(Bs + (k + 2) * 68 + tc);
        float4 b3 = *(const float4*)(Bs + (k + 3) * 68 + tc);
#pragma unroll
        for (int i = 0; i < 4; i++) {
            float4 a = *(const float4*)(As + (tr + i) * K + k);
            acc[i][0] += a.x * b0.x + a.y * b1.x + a.z * b2.x + a.w * b3.x;
            acc[i][1] += a.x * b0.y + a.y * b1.y + a.z * b2.y + a.w * b3.y;
            acc[i][2] += a.x * b0.z + a.y * b1.z + a.z * b2.z + a.w * b3.z;
            acc[i][3] += a.x * b0.w + a.y * b1.w + a.z * b2.w + a.w * b3.w;
        }
    }
    float4 bias = *(const float4*)(b + c0 + tc);
#pragma unroll
    for (int i = 0; i < 4; i++) {
        int r = r0 + tr + i;
        if (r < M) {
            float4 o;
            o.x = acc[i][0] + bias.x;
            o.y = acc[i][1] + bias.y;
            o.z = acc[i][2] + bias.z;
            o.w = acc[i][3] + bias.w;
            if (RELU) {
                o.x = fmaxf(o.x, 0.f); o.y = fmaxf(o.y, 0.f);
                o.z = fmaxf(o.z, 0.f); o.w = fmaxf(o.w, 0.f);
            }
            *(float4*)(out + (size_t)r * 128 + c0 + tc) = o;
        }
    }
}

// ---------------- per-node kernels ----------------
__global__ void ent_kernel(const float* __restrict__ h,
                           const float* __restrict__ entrot,
                           float* __restrict__ z, int N) {
    int n = blockIdx.x * blockDim.x + threadIdx.x;
    if (n >= N) return;
    float4 hv = *(const float4*)(h + n * 128);
    float xin[4] = {tanhf(hv.x) * PI_HALF, tanhf(hv.y) * PI_HALF,
                    tanhf(hv.z) * PI_HALF, tanhf(hv.w) * PI_HALF};
    float zz[4];
    entangle_circ(xin, entrot, zz);
    *(float4*)(z + n * 4) = make_float4(zz[0], zz[1], zz[2], zz[3]);
}

// Warp per node: q/k projections (+tanh) and x_comb update using precomputed z.
__global__ void node_proj_kernel(const float* __restrict__ h,
                                 float* __restrict__ xc,
                                 const float* __restrict__ attqW, const float* __restrict__ attqb,
                                 const float* __restrict__ attkW, const float* __restrict__ attkb,
                                 const float* __restrict__ qprojW, const float* __restrict__ qprojb,
                                 const float* __restrict__ z,
                                 float* __restrict__ qout, float* __restrict__ kout, int N) {
    int gwid = (blockIdx.x * blockDim.x + threadIdx.x) >> 5;
    int lane = threadIdx.x & 31;
    if (gwid >= N) return;
    const float4 hv = *(const float4*)(h + gwid * 128 + lane * 4);
    float acc[8];
#pragma unroll
    for (int j = 0; j < 8; j++) {
        const float* Wr = (j < 4 ? attqW + j * 128 : attkW + (j - 4) * 128) + lane * 4;
        float4 w = *(const float4*)Wr;
        acc[j] = hv.x * w.x + hv.y * w.y + hv.z * w.z + hv.w * w.w;
    }
#pragma unroll
    for (int off = 16; off; off >>= 1)
#pragma unroll
        for (int j = 0; j < 8; j++)
            acc[j] += __shfl_xor_sync(0xffffffffu, acc[j], off);
    if (lane < 4) {
        qout[gwid * 4 + lane] = tanhf(acc[lane] + attqb[lane]) * PI_HALF;
        kout[gwid * 4 + lane] = tanhf(acc[4 + lane] + attkb[lane]) * PI_HALF;
    }
    float4 zv = *(const float4*)(z + gwid * 4);
    float4 xcv = *(const float4*)(xc + gwid * 128 + lane * 4);
    float res[4] = {xcv.x, xcv.y, xcv.z, xcv.w};
#pragma unroll
    for (int i = 0; i < 4; i++) {
        int c = lane * 4 + i;
        float4 qp = *(const float4*)(qprojW + c * 4);
        res[i] += zv.x * qp.x + zv.y * qp.y + zv.z * qp.z + zv.w * qp.w + qprojb[c];
    }
    *(float4*)(xc + gwid * 128 + lane * 4) = make_float4(res[0], res[1], res[2], res[3]);
}

// Thread per node: psi = H^4 RY(q)|0>, kcs = (cos,sin)(k_i/2). Hoists all
// per-node sincos and gates out of the edge loop.
__global__ void edge_prep_kernel(const float* __restrict__ q,
                                 const float* __restrict__ k,
                                 float* __restrict__ psi, float* __restrict__ kcs, int N) {
    int n = blockIdx.x * blockDim.x + threadIdx.x;
    if (n >= N) return;
    float4 qa = *(const float4*)(q + n * 4);
    float qq[4] = {qa.x, qa.y, qa.z, qa.w};
    float2 s[16];
    init_state(s);
    ry_all(s, qq);
    ap_h<8>(s); ap_h<4>(s); ap_h<2>(s); ap_h<1>(s);
    float4* po = (float4*)(psi + n * 32);
#pragma unroll
    for (int i = 0; i < 8; i++)
        po[i] = make_float4(s[2 * i].x, s[2 * i].y, s[2 * i + 1].x, s[2 * i + 1].y);
    float4 ka = *(const float4*)(k + n * 4);
    float kk[4] = {ka.x, ka.y, ka.z, ka.w};
    float cs[8];
#pragma unroll
    for (int i = 0; i < 4; i++)
        __sincosf(kk[i] * 0.5f, &cs[2 * i + 1], &cs[2 * i]);
    float4* ko = (float4*)(kcs + n * 8);
    ko[0] = make_float4(cs[0], cs[1], cs[2], cs[3]);
    ko[1] = make_float4(cs[4], cs[5], cs[6], cs[7]);
}

// One thread per CSR entry: CRYs + Rot + weighted |.|^2 + exp. No sincos.
__global__ void edge_score_kernel(const float* __restrict__ psi,
                                  const float* __restrict__ kcs,
                                  const int* __restrict__ csr_src,
                                  const int* __restrict__ csr_dst, int Et,
                                  const float* __restrict__ attrot,
                                  float* __restrict__ att, float* __restrict__ sumptr) {
    int i = blockIdx.x * blockDim.x + threadIdx.x;
    float es = 0.f;
    if (i < Et) {
        int sN = csr_src[i], dN = csr_dst[i];
        float2 s[16];
        const float4* pp = (const float4*)(psi + sN * 32);
#pragma unroll
        for (int j = 0; j < 8; j++) {
            float4 v = pp[j];
            s[2 * j]     = make_float2(v.x, v.y);
            s[2 * j + 1] = make_float2(v.z, v.w);
        }
        float4 cs0 = *(const float4*)(kcs + dN * 8);
        float4 cs1 = *(const float4*)(kcs + dN * 8 + 4);
        ap_cry<8, 4>(s, cs0.x, cs0.y);
        ap_cry<4, 2>(s, cs0.z, cs0.w);
        ap_cry<2, 1>(s, cs1.x, cs1.y);
        ap_cry<1, 8>(s, cs1.z, cs1.w);
        rot_all(s, attrot);
        float score = 0.f;
#pragma unroll
        for (int j = 0; j < 16; j++) {
            float n = s[j].x * s[j].x + s[j].y * s[j].y;
            score += n * (1.0f - 0.5f * (float)__popc(j));
        }
        es = expf(score);
        att[i] = es;
    }
    float v = es;
#pragma unroll
    for (int off = 16; off; off >>= 1) v += __shfl_xor_sync(0xffffffffu, v, off);
    __shared__ float sred[8];
    int lane = threadIdx.x & 31, warp = threadIdx.x >> 5;
    if (lane == 0) sred[warp] = v;
    __syncthreads();
    if (threadIdx.x == 0) {
        float t = 0.f;
#pragma unroll
        for (int j = 0; j < 8; j++) t += sred[j];
        atomicAdd(sumptr, t);
    }
}

// Warp per node: atomic-free CSR gather + fused ReLU. att is CSR-ordered.
__global__ void aggregate_kernel(const float* __restrict__ att,
                                 const float* __restrict__ sumptr,
                                 const float* __restrict__ xc,
                                 const int* __restrict__ rowptr,
                                 const int* __restrict__ csr_src,
                                 float* __restrict__ hn, int N) {
    int n = (blockIdx.x * blockDim.x + threadIdx.x) >> 5;
    int lane = threadIdx.x & 31;
    if (n >= N) return;
    float inv = 1.0f / sumptr[0];
    int beg = rowptr[n], end = rowptr[n + 1];
    float4 acc = make_float4(0.f, 0.f, 0.f, 0.f);
#pragma unroll 2
    for (int i = beg; i < end; i++) {
        int s = csr_src[i];
        float w = att[i] * inv;
        float4 v = *(const float4*)(xc + s * 128 + lane * 4);
        acc.x += w * v.x; acc.y += w * v.y; acc.z += w * v.z; acc.w += w * v.w;
    }
    acc.x = fmaxf(acc.x, 0.f); acc.y = fmaxf(acc.y, 0.f);
    acc.z = fmaxf(acc.z, 0.f); acc.w = fmaxf(acc.w, 0.f);
    *(float4*)(hn + n * 128 + lane * 4) = acc;
}

// Warp per node: pq projection only.
__global__ void path_proj_kernel(const float* __restrict__ h,
                                 const float* __restrict__ piW, const float* __restrict__ pib,
                                 float* __restrict__ pq, int N) {
    int n = (blockIdx.x * blockDim.x + threadIdx.x) >> 5;
    int lane = threadIdx.x & 31;
    if (n >= N) return;
    float4 hv = *(const float4*)(h + n * 128 + lane * 4);
    float acc[4];
#pragma unroll
    for (int j = 0; j < 4; j++) {
        float4 w = *(const float4*)(piW + j * 128 + lane * 4);
        acc[j] = hv.x * w.x + hv.y * w.y + hv.z * w.z + hv.w * w.w;
    }
#pragma unroll
    for (int off = 16; off; off >>= 1)
#pragma unroll
        for (int j = 0; j < 4; j++)
            acc[j] += __shfl_xor_sync(0xffffffffu, acc[j], off);
    if (lane < 4)
        pq[n * 4 + lane] = tanhf(acc[lane] + pib[lane]) * PI_HALF;
}

// Thread per node: path circuit + collapsed epilogue out = c0 + M @ z.
__global__ void path_out_kernel(const float* __restrict__ pq,
                                const float* __restrict__ pathrot,
                                const float* __restrict__ M, const float* __restrict__ c0,
                                float* __restrict__ out, int N) {
    int n = blockIdx.x * blockDim.x + threadIdx.x;
    if (n >= N) return;
    float4 p = *(const float4*)(pq + n * 4);
    float xin[4] = {p.x, p.y, p.z, p.w};
    float z[4];
    path_circ(xin, pathrot, z);
    float4* o4 = (float4*)(out + n * 32);
#pragma unroll
    for (int g = 0; g < 8; g++) {
        float4 r;
        float* rp = (float*)&r;
#pragma unroll
        for (int i = 0; i < 4; i++) {
            int o = g * 4 + i;
            float4 m = *(const float4*)(M + o * 4);
            rp[i] = c0[o] + z[0] * m.x + z[1] * m.y + z[2] * m.z + z[3] * m.w;
        }
        o4[g] = r;
    }
}

// ---------------- host ----------------
extern "C" void kernel_launch(void* const* d_in, const int* in_sizes, int n_in,
                              void* d_out, int out_size) {
    const float* x        = (const float*)d_in[0];
    const float* W_in     = (const float*)d_in[1];
    const float* b_in     = (const float*)d_in[2];
    const float* lin_W    = (const float*)d_in[3];
    const float* lin_b    = (const float*)d_in[4];
    const float* qproj_W  = (const float*)d_in[5];
    const float* qproj_b  = (const float*)d_in[6];
    const float* ent_p    = (const float*)d_in[7];
    const float* attq_W   = (const float*)d_in[8];
    const float* attq_b   = (const float*)d_in[9];
    const float* attk_W   = (const float*)d_in[10];
    const float* attk_b   = (const float*)d_in[11];
    const float* att_qp   = (const float*)d_in[12];
    const float* path_p   = (const float*)d_in[13];
    const float* pi_W     = (const float*)d_in[14];
    const float* pi_b     = (const float*)d_in[15];
    const float* po_W     = (const float*)d_in[16];
    const float* po_b     = (const float*)d_in[17];
    const float* out_W    = (const float*)d_in[18];
    const float* out_b    = (const float*)d_in[19];
    const int*   ei       = (const int*)d_in[20];
    float* out = (float*)d_out;

    int N  = in_sizes[0] / 64;
    int E0 = in_sizes[20] / 2;
    int Et = E0 + N;

    float *bufA, *bufB, *xc, *qb, *kb, *zb, *psi, *kcs, *att, *sum, *rot, *Mp, *c0p;
    float *wt0, *wt1;
    int *deg, *rowptr, *cursor, *csrs, *csrd;
    cudaGetSymbolAddress((void**)&bufA,   g_bufA);
    cudaGetSymbolAddress((void**)&bufB,   g_bufB);
    cudaGetSymbolAddress((void**)&xc,     g_xc);
    cudaGetSymbolAddress((void**)&qb,     g_q);
    cudaGetSymbolAddress((void**)&kb,     g_k);
    cudaGetSymbolAddress((void**)&zb,     g_z);
    cudaGetSymbolAddress((void**)&psi,    g_psi);
    cudaGetSymbolAddress((void**)&kcs,    g_kcs);
    cudaGetSymbolAddress((void**)&att,    g_att);
    cudaGetSymbolAddress((void**)&sum,    g_sum);
    cudaGetSymbolAddress((void**)&rot,    g_rot);
    cudaGetSymbolAddress((void**)&deg,    g_deg);
    cudaGetSymbolAddress((void**)&rowptr, g_rowptr);
    cudaGetSymbolAddress((void**)&cursor, g_cursor);
    cudaGetSymbolAddress((void**)&csrs,   g_csr_src);
    cudaGetSymbolAddress((void**)&csrd,   g_csr_dst);
    cudaGetSymbolAddress((void**)&Mp,     g_M);
    cudaGetSymbolAddress((void**)&c0p,    g_c0);
    cudaGetSymbolAddress((void**)&wt0,    g_Wt0);
    cudaGetSymbolAddress((void**)&wt1,    g_Wt1);

    const int SMEM_G64  = (64 * 64 + 64 * 68) * 4;    // 33792
    const int SMEM_G128 = (64 * 128 + 128 * 68) * 4;  // 67584
    cudaFuncSetAttribute(gemm_tile_kernel<64, true>,
                         cudaFuncAttributeMaxDynamicSharedMemorySize, SMEM_G64);
    cudaFuncSetAttribute(gemm_tile_kernel<128, false>,
                         cudaFuncAttributeMaxDynamicSharedMemorySize, SMEM_G128);

    prep_kernel<<<1, 64>>>(att_qp, ent_p, path_p, rot, sum);
    path_precomp_kernel<<<1, 128>>>(po_W, po_b, out_W, out_b, Mp, c0p);
    transpose_kernel<<<(128 * 64 + 255) / 256, 256>>>(W_in, wt0, 128, 64);
    transpose_kernel<<<(2 * 128 * 128 + 255) / 256, 256>>>(lin_W, wt1, 256, 128);
    // note: lin_W is [2][128][128]; transposing as C=256 rows of K=128 gives
    // Wt[k][c'] with c' in 0..255; layer l uses columns — WRONG. Do per-layer:
    // (overwrite with two correct calls below)
    transpose_kernel<<<(128 * 128 + 255) / 256, 256>>>(lin_W, wt1, 128, 128);
    transpose_kernel<<<(128 * 128 + 255) / 256, 256>>>(lin_W + 128 * 128,
                                                       wt1 + 128 * 128, 128, 128);

    // CSR by dst (edge set constant across layers; build once)
    cudaMemsetAsync(deg, 0, (size_t)(N + 1) * sizeof(int), 0);
    csr_count_kernel<<<(Et + 255) / 256, 256>>>(ei, E0, N, deg);
    csr_scan_kernel<<<1, 1024>>>(deg, rowptr, cursor, N);
    csr_fill_kernel<<<(Et + 255) / 256, 256>>>(ei, E0, N, cursor, csrs, csrd);

    // h0 = relu(x @ W_in^T + b_in)
    {
        dim3 g((N + 63) / 64, 2);
        gemm_tile_kernel<64, true><<<g, 256, SMEM_G64>>>(x, wt0, b_in, bufA, N);
    }

    float* hcur = bufA;
    float* hnext = bufB;
    for (int l = 0; l < 2; l++) {
        {
            dim3 g((N + 63) / 64, 2);
            gemm_tile_kernel<128, false><<<g, 256, SMEM_G128>>>(
                hcur, wt1 + l * 128 * 128, lin_b + l * 128, xc, N);
        }
        ent_kernel<<<(N + 127) / 128, 128>>>(hcur, rot + 64 + l * 64, zb, N);
        node_proj_kernel<<<(N * 32 + 255) / 256, 256>>>(
            hcur, xc,
            attq_W + l * 4 * 128, attq_b + l * 4,
            attk_W + l * 4 * 128, attk_b + l * 4,
            qproj_W + l * 128 * 4, qproj_b + l * 128,
            zb, qb, kb, N);
        edge_prep_kernel<<<(N + 127) / 128, 128>>>(qb, kb, psi, kcs, N);
        edge_score_kernel<<<(Et + 255) / 256, 256>>>(
            psi, kcs, csrs, csrd, Et, rot + l * 32, att, sum + l);
        aggregate_kernel<<<(N * 32 + 255) / 256, 256>>>(
            att, sum + l, xc, rowptr, csrs, hnext, N);
        float* t = hcur; hcur = hnext; hnext = t;
    }

    path_proj_kernel<<<(N * 32 + 255) / 256, 256>>>(hcur, pi_W, pi_b, qb, N);
    path_out_kernel<<<(N + 127) / 128, 128>>>(qb, rot + 192, Mp, c0p, out, N);
}

// round 9
// speedup vs baseline: 1.9771x; 1.1876x over previous
#include <cuda_runtime.h>
#include <cuda_bf16.h>

#define PI_HALF 1.57079632679489662f
#define NMAX 20000
#define EMAX 300000

// ---------------- scratch (no allocation allowed) ----------------
__device__ float g_bufA[NMAX * 128];
__device__ float g_bufB[NMAX * 128];
__device__ float g_xc[NMAX * 128];
__device__ float g_q[NMAX * 4];
__device__ float g_k[NMAX * 4];
__device__ float g_z[NMAX * 4];
__device__ float g_psi[NMAX * 32];       // per-node state after RY(q)+H (16 complex)
__device__ float g_kcs[NMAX * 8];        // per-node cos/sin of k[i]/2
__device__ float g_att[EMAX + NMAX];
__device__ float g_sum[2];
__device__ float g_rot[36 * 8];          // 36 complex 2x2 matrices
__device__ int   g_deg[NMAX + 1];
__device__ int   g_rowptr[NMAX + 1];
__device__ int   g_cursor[NMAX + 1];
__device__ int   g_csr_src[EMAX + NMAX];
__device__ int   g_csr_dst[EMAX + NMAX];
__device__ float g_M[32 * 4];
__device__ float g_c0[32];
__device__ float g_Wt0[64 * 128];        // W_in^T  [K=64][C=128]
__device__ float g_Wt1[2 * 128 * 128];   // lin_W^T [K=128][C=128] per layer

// ---------------- complex helpers ----------------
__device__ __forceinline__ float2 cmul(float2 a, float2 b) {
    return make_float2(a.x * b.x - a.y * b.y, a.x * b.y + a.y * b.x);
}

template<int M>
__device__ __forceinline__ void ap_ry(float2* s, float c, float sn) {
#pragma unroll
    for (int i = 0; i < 16; i++) {
        if (i & M) continue;
        float2 a = s[i], b = s[i | M];
        s[i]     = make_float2(c * a.x - sn * b.x, c * a.y - sn * b.y);
        s[i | M] = make_float2(sn * a.x + c * b.x, sn * a.y + c * b.y);
    }
}

template<int M>
__device__ __forceinline__ void ap_h(float2* s) {
    const float r = 0.70710678118654752f;
#pragma unroll
    for (int i = 0; i < 16; i++) {
        if (i & M) continue;
        float2 a = s[i], b = s[i | M];
        s[i]     = make_float2((a.x + b.x) * r, (a.y + b.y) * r);
        s[i | M] = make_float2((a.x - b.x) * r, (a.y - b.y) * r);
    }
}

template<int MC, int MT>
__device__ __forceinline__ void ap_cry(float2* s, float c, float sn) {
#pragma unroll
    for (int i = 0; i < 16; i++) {
        if (!(i & MC) || (i & MT)) continue;
        float2 a = s[i], b = s[i | MT];
        s[i]      = make_float2(c * a.x - sn * b.x, c * a.y - sn * b.y);
        s[i | MT] = make_float2(sn * a.x + c * b.x, sn * a.y + c * b.y);
    }
}

template<int MC, int MT>
__device__ __forceinline__ void ap_cnot(float2* s) {
#pragma unroll
    for (int i = 0; i < 16; i++) {
        if (!(i & MC) || (i & MT)) continue;
        float2 t = s[i];
        s[i] = s[i | MT];
        s[i | MT] = t;
    }
}

template<int M>
__device__ __forceinline__ void ap_rot(float2* s, const float* __restrict__ u) {
    float2 u00 = make_float2(u[0], u[1]);
    float2 u01 = make_float2(u[2], u[3]);
    float2 u10 = make_float2(u[4], u[5]);
    float2 u11 = make_float2(u[6], u[7]);
#pragma unroll
    for (int i = 0; i < 16; i++) {
        if (i & M) continue;
        float2 a = s[i], b = s[i | M];
        float2 ra = cmul(u00, a), rb = cmul(u01, b);
        float2 sa = cmul(u10, a), sb = cmul(u11, b);
        s[i]     = make_float2(ra.x + rb.x, ra.y + rb.y);
        s[i | M] = make_float2(sa.x + sb.x, sa.y + sb.y);
    }
}

__device__ __forceinline__ void init_state(float2* s) {
#pragma unroll
    for (int i = 0; i < 16; i++) s[i] = make_float2(0.f, 0.f);
    s[0] = make_float2(1.f, 0.f);
}

__device__ __forceinline__ void zexp4(const float2* s, float z[4]) {
    z[0] = z[1] = z[2] = z[3] = 0.f;
#pragma unroll
    for (int i = 0; i < 16; i++) {
        float n = s[i].x * s[i].x + s[i].y * s[i].y;
        z[0] += (i & 8) ? -n : n;
        z[1] += (i & 4) ? -n : n;
        z[2] += (i & 2) ? -n : n;
        z[3] += (i & 1) ? -n : n;
    }
}

__device__ __forceinline__ void ry_all(float2* s, const float a[4]) {
    float c, sn;
    __sincosf(a[0] * 0.5f, &sn, &c); ap_ry<8>(s, c, sn);
    __sincosf(a[1] * 0.5f, &sn, &c); ap_ry<4>(s, c, sn);
    __sincosf(a[2] * 0.5f, &sn, &c); ap_ry<2>(s, c, sn);
    __sincosf(a[3] * 0.5f, &sn, &c); ap_ry<1>(s, c, sn);
}

__device__ __forceinline__ void rot_all(float2* s, const float* __restrict__ rm) {
    ap_rot<8>(s, rm);
    ap_rot<4>(s, rm + 8);
    ap_rot<2>(s, rm + 16);
    ap_rot<1>(s, rm + 24);
}

// ---------------- circuits ----------------
__device__ __forceinline__ void entangle_circ(const float xin[4],
                                              const float* __restrict__ rot,
                                              float z[4]) {
    float2 s[16];
    init_state(s);
    ry_all(s, xin);
#pragma unroll
    for (int l = 0; l < 2; l++) {
        ap_cnot<8, 4>(s); ap_cnot<4, 2>(s); ap_cnot<2, 1>(s);
        rot_all(s, rot + l * 32);
        ap_cnot<8, 1>(s);
    }
    zexp4(s, z);
}

__device__ __forceinline__ void path_circ(const float xin[4],
                                          const float* __restrict__ rot,
                                          float z[4]) {
    float2 s[16];
    init_state(s);
    ap_h<8>(s); ap_h<4>(s); ap_h<2>(s); ap_h<1>(s);
    ry_all(s, xin);
#pragma unroll
    for (int l = 0; l < 3; l++) {
        rot_all(s, rot + l * 32);
        ap_cnot<8, 4>(s); ap_cnot<4, 2>(s); ap_cnot<2, 1>(s);
    }
    zexp4(s, z);
}

// ---------------- small prep kernels ----------------
__global__ void prep_kernel(const float* __restrict__ attqp,
                            const float* __restrict__ entp,
                            const float* __restrict__ pathp,
                            float* __restrict__ rot, float* __restrict__ sums) {
    int t = threadIdx.x;
    if (t < 2) sums[t] = 0.f;
    if (t >= 36) return;
    const float* p;
    if (t < 8)       p = attqp + t * 3;
    else if (t < 24) p = entp + (t - 8) * 3;
    else             p = pathp + (t - 24) * 3;
    float phi = p[0], th = p[1], om = p[2];
    float c, s;  sincosf(th * 0.5f, &s, &c);
    float a1 = (phi + om) * 0.5f, a2 = (phi - om) * 0.5f;
    float c1, s1, c2, s2;
    sincosf(a1, &s1, &c1);
    sincosf(a2, &s2, &c2);
    float* u = rot + t * 8;
    u[0] =  c * c1;  u[1] = -c * s1;
    u[2] = -s * c2;  u[3] = -s * s2;
    u[4] =  s * c2;  u[5] = -s * s2;
    u[6] =  c * c1;  u[7] =  c * s1;
}

__global__ void path_precomp_kernel(const float* __restrict__ poW,
                                    const float* __restrict__ pob,
                                    const float* __restrict__ outW,
                                    const float* __restrict__ outb,
                                    float* __restrict__ M, float* __restrict__ c0) {
    int o = threadIdx.x >> 2, j = threadIdx.x & 3;
    float m = 0.f;
    for (int k = 0; k < 128; k++) m += outW[o * 128 + k] * poW[k * 4 + j];
    M[o * 4 + j] = m;
    if (j == 0) {
        float cc = outb[o];
        for (int k = 0; k < 128; k++) cc += outW[o * 128 + k] * pob[k];
        c0[o] = cc;
    }
}

// W[C][K] -> Wt[K][C]
__global__ void transpose_kernel(const float* __restrict__ W, float* __restrict__ Wt,
                                 int C, int K) {
    int i = blockIdx.x * 256 + threadIdx.x;
    if (i >= C * K) return;
    int c = i / K, k = i % K;
    Wt[k * C + c] = W[i];
}

// ---- CSR build (once per launch) ----
__global__ void csr_count_kernel(const int* __restrict__ ei, int E0, int N,
                                 int* __restrict__ cnt) {
    int e = blockIdx.x * blockDim.x + threadIdx.x;
    if (e >= E0 + N) return;
    int d = (e < E0) ? ei[E0 + e] : e - E0;
    atomicAdd(&cnt[d], 1);
}

// 1024 threads, each owns IT contiguous elems; shuffle warp scan + block scan.
__global__ void csr_scan_kernel(const int* __restrict__ cnt,
                                int* __restrict__ rowptr, int* __restrict__ cursor,
                                int N) {
    const int IT = (NMAX + 1023) / 1024;   // 20
    __shared__ int wsum[32];
    int tid = threadIdx.x, lane = tid & 31, wid = tid >> 5;
    int base = tid * IT;
    int v[IT];
    int run = 0;
#pragma unroll
    for (int j = 0; j < IT; j++) {
        v[j] = run;
        int i = base + j;
        run += (i < N) ? cnt[i] : 0;
    }
    int s = run;
#pragma unroll
    for (int off = 1; off < 32; off <<= 1) {
        int t = __shfl_up_sync(0xffffffffu, s, off);
        if (lane >= off) s += t;
    }
    if (lane == 31) wsum[wid] = s;
    __syncthreads();
    if (wid == 0) {
        int w = wsum[lane];
        int ws = w;
#pragma unroll
        for (int off = 1; off < 32; off <<= 1) {
            int t = __shfl_up_sync(0xffffffffu, ws, off);
            if (lane >= off) ws += t;
        }
        wsum[lane] = ws - w;   // exclusive
    }
    __syncthreads();
    int offset = wsum[wid] + (s - run);
#pragma unroll
    for (int j = 0; j < IT; j++) {
        int i = base + j;
        if (i <= N) {
            int val = offset + v[j];
            rowptr[i] = val;
            cursor[i] = val;
        }
    }
}

__global__ void csr_fill_kernel(const int* __restrict__ ei, int E0, int N,
                                int* __restrict__ cursor,
                                int* __restrict__ csr_src, int* __restrict__ csr_dst) {
    int e = blockIdx.x * blockDim.x + threadIdx.x;
    if (e >= E0 + N) return;
    int s, d;
    if (e < E0) { s = ei[e]; d = ei[E0 + e]; }
    else        { s = d = e - E0; }
    int p = atomicAdd(&cursor[d], 1);
    csr_src[p] = s;
    csr_dst[p] = d;
}

// ---------------- register-tiled GEMM (optional fused z-projection) ----------------
// out[M][128] = act(in[M][K] @ Wt + b [+ z @ qpW^T + qpb]), Wt pre-transposed [K][128].
// 64x64 tile per block, 256 threads, 4x4 micro-tile.
template<int K, bool RELU, bool ZPROJ>
__global__ void gemm_tile_kernel(const float* __restrict__ in,
                                 const float* __restrict__ Wt,
                                 const float* __restrict__ b,
                                 const float* __restrict__ z,     // [M][4] or null
                                 const float* __restrict__ qpW,   // [128][4] or null
                                 const float* __restrict__ qpb,   // [128] or null
                                 float* __restrict__ out, int M) {
    extern __shared__ float sm[];
    float* As = sm;             // [64][K] row-major
    float* Bs = sm + 64 * K;    // [K][68]
    int tid = threadIdx.x;
    int r0 = blockIdx.x * 64;
    int c0 = blockIdx.y * 64;
    int nrows = min(64, M - r0);
    for (int idx = tid * 4; idx < 64 * K; idx += 1024) {
        int r = idx / K, k = idx % K;
        float4 v = make_float4(0.f, 0.f, 0.f, 0.f);
        if (r < nrows) v = *(const float4*)(in + (size_t)(r0 + r) * K + k);
        *(float4*)(As + r * K + k) = v;
    }
    for (int idx = tid * 4; idx < K * 64; idx += 1024) {
        int k = idx >> 6, c = idx & 63;
        float4 v = *(const float4*)(Wt + (size_t)k * 128 + c0 + c);
        *(float4*)(Bs + k * 68 + c) = v;
    }
    __syncthreads();
    int tr = (tid >> 4) * 4;
    int tc = (tid & 15) * 4;
    float acc[4][4];
#pragma unroll
    for (int i = 0; i < 4; i++)
#pragma unroll
        for (int j = 0; j < 4; j++) acc[i][j] = 0.f;
#pragma unroll 2
    for (int k = 0; k < K; k += 4) {
        float4 b0 = *(const float4*)(Bs + (k + 0) * 68 + tc);
        float4 b1 = *(const float4*)(Bs + (k + 1) * 68 + tc);
        float4 b2 = *(const float4*)(Bs + (k + 2) * 68 + tc);
        float4 b3 = *(const float4*)(Bs + (k + 3) * 68 + tc);
#pragma unroll
        for (int i = 0; i < 4; i++) {
            float4 a = *(const float4*)(As + (tr + i) * K + k);
            acc[i][0] += a.x * b0.x + a.y * b1.x + a.z * b2.x + a.w * b3.x;
            acc[i][1] += a.x * b0.y + a.y * b1.y + a.z * b2.y + a.w * b3.y;
            acc[i][2] += a.x * b0.z + a.y * b1.z + a.z * b2.z + a.w * b3.z;
            acc[i][3] += a.x * b0.w + a.y * b1.w + a.z * b2.w + a.w * b3.w;
        }
    }
    float4 bias = *(const float4*)(b + c0 + tc);
    float4 qw[4], qbias;
    if (ZPROJ) {
#pragma unroll
        for (int j = 0; j < 4; j++)
            qw[j] = *(const float4*)(qpW + (c0 + tc + j) * 4);
        qbias = *(const float4*)(qpb + c0 + tc);
    }
#pragma unroll
    for (int i = 0; i < 4; i++) {
        int r = r0 + tr + i;
        if (r < M) {
            float4 o;
            o.x = acc[i][0] + bias.x;
            o.y = acc[i][1] + bias.y;
            o.z = acc[i][2] + bias.z;
            o.w = acc[i][3] + bias.w;
            if (ZPROJ) {
                float4 zv = *(const float4*)(z + r * 4);
                o.x += zv.x * qw[0].x + zv.y * qw[0].y + zv.z * qw[0].z + zv.w * qw[0].w + qbias.x;
                o.y += zv.x * qw[1].x + zv.y * qw[1].y + zv.z * qw[1].z + zv.w * qw[1].w + qbias.y;
                o.z += zv.x * qw[2].x + zv.y * qw[2].y + zv.z * qw[2].z + zv.w * qw[2].w + qbias.z;
                o.w += zv.x * qw[3].x + zv.y * qw[3].y + zv.z * qw[3].z + zv.w * qw[3].w + qbias.w;
            }
            if (RELU) {
                o.x = fmaxf(o.x, 0.f); o.y = fmaxf(o.y, 0.f);
                o.z = fmaxf(o.z, 0.f); o.w = fmaxf(o.w, 0.f);
            }
            *(float4*)(out + (size_t)r * 128 + c0 + tc) = o;
        }
    }
}

// ---------------- per-node kernels ----------------
__global__ void ent_kernel(const float* __restrict__ h,
                           const float* __restrict__ entrot,
                           float* __restrict__ z, int N) {
    int n = blockIdx.x * blockDim.x + threadIdx.x;
    if (n >= N) return;
    float4 hv = *(const float4*)(h + n * 128);
    float xin[4] = {tanhf(hv.x) * PI_HALF, tanhf(hv.y) * PI_HALF,
                    tanhf(hv.z) * PI_HALF, tanhf(hv.w) * PI_HALF};
    float zz[4];
    entangle_circ(xin, entrot, zz);
    *(float4*)(z + n * 4) = make_float4(zz[0], zz[1], zz[2], zz[3]);
}

// Warp per node: q/k projections (+tanh) only.
__global__ void qk_proj_kernel(const float* __restrict__ h,
                               const float* __restrict__ attqW, const float* __restrict__ attqb,
                               const float* __restrict__ attkW, const float* __restrict__ attkb,
                               float* __restrict__ qout, float* __restrict__ kout, int N) {
    int gwid = (blockIdx.x * blockDim.x + threadIdx.x) >> 5;
    int lane = threadIdx.x & 31;
    if (gwid >= N) return;
    const float4 hv = *(const float4*)(h + gwid * 128 + lane * 4);
    float acc[8];
#pragma unroll
    for (int j = 0; j < 8; j++) {
        const float* Wr = (j < 4 ? attqW + j * 128 : attkW + (j - 4) * 128) + lane * 4;
        float4 w = *(const float4*)Wr;
        acc[j] = hv.x * w.x + hv.y * w.y + hv.z * w.z + hv.w * w.w;
    }
#pragma unroll
    for (int off = 16; off; off >>= 1)
#pragma unroll
        for (int j = 0; j < 8; j++)
            acc[j] += __shfl_xor_sync(0xffffffffu, acc[j], off);
    if (lane < 4) {
        qout[gwid * 4 + lane] = tanhf(acc[lane] + attqb[lane]) * PI_HALF;
        kout[gwid * 4 + lane] = tanhf(acc[4 + lane] + attkb[lane]) * PI_HALF;
    }
}

// Thread per node: psi = H^4 RY(q)|0>, kcs = (cos,sin)(k_i/2).
__global__ void edge_prep_kernel(const float* __restrict__ q,
                                 const float* __restrict__ k,
                                 float* __restrict__ psi, float* __restrict__ kcs, int N) {
    int n = blockIdx.x * blockDim.x + threadIdx.x;
    if (n >= N) return;
    float4 qa = *(const float4*)(q + n * 4);
    float qq[4] = {qa.x, qa.y, qa.z, qa.w};
    float2 s[16];
    init_state(s);
    ry_all(s, qq);
    ap_h<8>(s); ap_h<4>(s); ap_h<2>(s); ap_h<1>(s);
    float4* po = (float4*)(psi + n * 32);
#pragma unroll
    for (int i = 0; i < 8; i++)
        po[i] = make_float4(s[2 * i].x, s[2 * i].y, s[2 * i + 1].x, s[2 * i + 1].y);
    float4 ka = *(const float4*)(k + n * 4);
    float kk[4] = {ka.x, ka.y, ka.z, ka.w};
    float cs[8];
#pragma unroll
    for (int i = 0; i < 4; i++)
        __sincosf(kk[i] * 0.5f, &cs[2 * i + 1], &cs[2 * i]);
    float4* ko = (float4*)(kcs + n * 8);
    ko[0] = make_float4(cs[0], cs[1], cs[2], cs[3]);
    ko[1] = make_float4(cs[4], cs[5], cs[6], cs[7]);
}

// One thread per CSR entry: CRYs + Rot + weighted |.|^2 + exp. No sincos.
__global__ void edge_score_kernel(const float* __restrict__ psi,
                                  const float* __restrict__ kcs,
                                  const int* __restrict__ csr_src,
                                  const int* __restrict__ csr_dst, int Et,
                                  const float* __restrict__ attrot,
                                  float* __restrict__ att, float* __restrict__ sumptr) {
    int i = blockIdx.x * blockDim.x + threadIdx.x;
    float es = 0.f;
    if (i < Et) {
        int sN = csr_src[i], dN = csr_dst[i];
        float2 s[16];
        const float4* pp = (const float4*)(psi + sN * 32);
#pragma unroll
        for (int j = 0; j < 8; j++) {
            float4 v = pp[j];
            s[2 * j]     = make_float2(v.x, v.y);
            s[2 * j + 1] = make_float2(v.z, v.w);
        }
        float4 cs0 = *(const float4*)(kcs + dN * 8);
        float4 cs1 = *(const float4*)(kcs + dN * 8 + 4);
        ap_cry<8, 4>(s, cs0.x, cs0.y);
        ap_cry<4, 2>(s, cs0.z, cs0.w);
        ap_cry<2, 1>(s, cs1.x, cs1.y);
        ap_cry<1, 8>(s, cs1.z, cs1.w);
        rot_all(s, attrot);
        float score = 0.f;
#pragma unroll
        for (int j = 0; j < 16; j++) {
            float n = s[j].x * s[j].x + s[j].y * s[j].y;
            score += n * (1.0f - 0.5f * (float)__popc(j));
        }
        es = expf(score);
        att[i] = es;
    }
    float v = es;
#pragma unroll
    for (int off = 16; off; off >>= 1) v += __shfl_xor_sync(0xffffffffu, v, off);
    __shared__ float sred[8];
    int lane = threadIdx.x & 31, warp = threadIdx.x >> 5;
    if (lane == 0) sred[warp] = v;
    __syncthreads();
    if (threadIdx.x == 0) {
        float t = 0.f;
#pragma unroll
        for (int j = 0; j < 8; j++) t += sred[j];
        atomicAdd(sumptr, t);
    }
}

// Warp per node: atomic-free CSR gather + fused ReLU, 4-deep pipelined.
__global__ void aggregate_kernel(const float* __restrict__ att,
                                 const float* __restrict__ sumptr,
                                 const float* __restrict__ xc,
                                 const int* __restrict__ rowptr,
                                 const int* __restrict__ csr_src,
                                 float* __restrict__ hn, int N) {
    int n = (blockIdx.x * blockDim.x + threadIdx.x) >> 5;
    int lane = threadIdx.x & 31;
    if (n >= N) return;
    int beg = rowptr[n], end = rowptr[n + 1];
    float4 acc = make_float4(0.f, 0.f, 0.f, 0.f);
    int i = beg;
    for (; i + 4 <= end; i += 4) {
        int s0 = csr_src[i],     s1 = csr_src[i + 1];
        int s2 = csr_src[i + 2], s3 = csr_src[i + 3];
        float w0 = att[i],     w1 = att[i + 1];
        float w2 = att[i + 2], w3 = att[i + 3];
        float4 v0 = *(const float4*)(xc + s0 * 128 + lane * 4);
        float4 v1 = *(const float4*)(xc + s1 * 128 + lane * 4);
        float4 v2 = *(const float4*)(xc + s2 * 128 + lane * 4);
        float4 v3 = *(const float4*)(xc + s3 * 128 + lane * 4);
        acc.x += w0 * v0.x + w1 * v1.x + w2 * v2.x + w3 * v3.x;
        acc.y += w0 * v0.y + w1 * v1.y + w2 * v2.y + w3 * v3.y;
        acc.z += w0 * v0.z + w1 * v1.z + w2 * v2.z + w3 * v3.z;
        acc.w += w0 * v0.w + w1 * v1.w + w2 * v2.w + w3 * v3.w;
    }
    for (; i < end; i++) {
        int s = csr_src[i];
        float w = att[i];
        float4 v = *(const float4*)(xc + s * 128 + lane * 4);
        acc.x += w * v.x; acc.y += w * v.y; acc.z += w * v.z; acc.w += w * v.w;
    }
    float inv = 1.0f / sumptr[0];
    acc.x = fmaxf(acc.x * inv, 0.f); acc.y = fmaxf(acc.y * inv, 0.f);
    acc.z = fmaxf(acc.z * inv, 0.f); acc.w = fmaxf(acc.w * inv, 0.f);
    *(float4*)(hn + n * 128 + lane * 4) = acc;
}

// Warp per node: pq projection only.
__global__ void path_proj_kernel(const float* __restrict__ h,
                                 const float* __restrict__ piW, const float* __restrict__ pib,
                                 float* __restrict__ pq, int N) {
    int n = (blockIdx.x * blockDim.x + threadIdx.x) >> 5;
    int lane = threadIdx.x & 31;
    if (n >= N) return;
    float4 hv = *(const float4*)(h + n * 128 + lane * 4);
    float acc[4];
#pragma unroll
    for (int j = 0; j < 4; j++) {
        float4 w = *(const float4*)(piW + j * 128 + lane * 4);
        acc[j] = hv.x * w.x + hv.y * w.y + hv.z * w.z + hv.w * w.w;
    }
#pragma unroll
    for (int off = 16; off; off >>= 1)
#pragma unroll
        for (int j = 0; j < 4; j++)
            acc[j] += __shfl_xor_sync(0xffffffffu, acc[j], off);
    if (lane < 4)
        pq[n * 4 + lane] = tanhf(acc[lane] + pib[lane]) * PI_HALF;
}

// Thread per node: path circuit + collapsed epilogue out = c0 + M @ z.
__global__ void path_out_kernel(const float* __restrict__ pq,
                                const float* __restrict__ pathrot,
                                const float* __restrict__ M, const float* __restrict__ c0,
                                float* __restrict__ out, int N) {
    int n = blockIdx.x * blockDim.x + threadIdx.x;
    if (n >= N) return;
    float4 p = *(const float4*)(pq + n * 4);
    float xin[4] = {p.x, p.y, p.z, p.w};
    float z[4];
    path_circ(xin, pathrot, z);
    float4* o4 = (float4*)(out + n * 32);
#pragma unroll
    for (int g = 0; g < 8; g++) {
        float4 r;
        float* rp = (float*)&r;
#pragma unroll
        for (int i = 0; i < 4; i++) {
            int o = g * 4 + i;
            float4 m = *(const float4*)(M + o * 4);
            rp[i] = c0[o] + z[0] * m.x + z[1] * m.y + z[2] * m.z + z[3] * m.w;
        }
        o4[g] = r;
    }
}

// ---------------- host ----------------
extern "C" void kernel_launch(void* const* d_in, const int* in_sizes, int n_in,
                              void* d_out, int out_size) {
    const float* x        = (const float*)d_in[0];
    const float* W_in     = (const float*)d_in[1];
    const float* b_in     = (const float*)d_in[2];
    const float* lin_W    = (const float*)d_in[3];
    const float* lin_b    = (const float*)d_in[4];
    const float* qproj_W  = (const float*)d_in[5];
    const float* qproj_b  = (const float*)d_in[6];
    const float* ent_p    = (const float*)d_in[7];
    const float* attq_W   = (const float*)d_in[8];
    const float* attq_b   = (const float*)d_in[9];
    const float* attk_W   = (const float*)d_in[10];
    const float* attk_b   = (const float*)d_in[11];
    const float* att_qp   = (const float*)d_in[12];
    const float* path_p   = (const float*)d_in[13];
    const float* pi_W     = (const float*)d_in[14];
    const float* pi_b     = (const float*)d_in[15];
    const float* po_W     = (const float*)d_in[16];
    const float* po_b     = (const float*)d_in[17];
    const float* out_W    = (const float*)d_in[18];
    const float* out_b    = (const float*)d_in[19];
    const int*   ei       = (const int*)d_in[20];
    float* out = (float*)d_out;

    int N  = in_sizes[0] / 64;
    int E0 = in_sizes[20] / 2;
    int Et = E0 + N;

    float *bufA, *bufB, *xc, *qb, *kb, *zb, *psi, *kcs, *att, *sum, *rot, *Mp, *c0p;
    float *wt0, *wt1;
    int *deg, *rowptr, *cursor, *csrs, *csrd;
    cudaGetSymbolAddress((void**)&bufA,   g_bufA);
    cudaGetSymbolAddress((void**)&bufB,   g_bufB);
    cudaGetSymbolAddress((void**)&xc,     g_xc);
    cudaGetSymbolAddress((void**)&qb,     g_q);
    cudaGetSymbolAddress((void**)&kb,     g_k);
    cudaGetSymbolAddress((void**)&zb,     g_z);
    cudaGetSymbolAddress((void**)&psi,    g_psi);
    cudaGetSymbolAddress((void**)&kcs,    g_kcs);
    cudaGetSymbolAddress((void**)&att,    g_att);
    cudaGetSymbolAddress((void**)&sum,    g_sum);
    cudaGetSymbolAddress((void**)&rot,    g_rot);
    cudaGetSymbolAddress((void**)&deg,    g_deg);
    cudaGetSymbolAddress((void**)&rowptr, g_rowptr);
    cudaGetSymbolAddress((void**)&cursor, g_cursor);
    cudaGetSymbolAddress((void**)&csrs,   g_csr_src);
    cudaGetSymbolAddress((void**)&csrd,   g_csr_dst);
    cudaGetSymbolAddress((void**)&Mp,     g_M);
    cudaGetSymbolAddress((void**)&c0p,    g_c0);
    cudaGetSymbolAddress((void**)&wt0,    g_Wt0);
    cudaGetSymbolAddress((void**)&wt1,    g_Wt1);

    // one-time stream/event setup (host resources, not device memory)
    static cudaStream_t s1 = nullptr;
    static cudaEvent_t evFork = nullptr, evF[2], evJ[2];
    if (!s1) {
        cudaStreamCreateWithFlags(&s1, cudaStreamNonBlocking);
        cudaEventCreateWithFlags(&evFork, cudaEventDisableTiming);
        for (int i = 0; i < 2; i++) {
            cudaEventCreateWithFlags(&evF[i], cudaEventDisableTiming);
            cudaEventCreateWithFlags(&evJ[i], cudaEventDisableTiming);
        }
    }

    const int SMEM_G64  = (64 * 64 + 64 * 68) * 4;    // 33792
    const int SMEM_G128 = (64 * 128 + 128 * 68) * 4;  // 67584
    cudaFuncSetAttribute(gemm_tile_kernel<64, true, false>,
                         cudaFuncAttributeMaxDynamicSharedMemorySize, SMEM_G64);
    cudaFuncSetAttribute(gemm_tile_kernel<128, false, true>,
                         cudaFuncAttributeMaxDynamicSharedMemorySize, SMEM_G128);

    // ---- fork s1: CSR build runs concurrently with prep + first GEMM ----
    cudaEventRecord(evFork, 0);
    cudaStreamWaitEvent(s1, evFork, 0);
    cudaMemsetAsync(deg, 0, (size_t)(N + 1) * sizeof(int), s1);
    csr_count_kernel<<<(Et + 255) / 256, 256, 0, s1>>>(ei, E0, N, deg);
    csr_scan_kernel<<<1, 1024, 0, s1>>>(deg, rowptr, cursor, N);
    csr_fill_kernel<<<(Et + 255) / 256, 256, 0, s1>>>(ei, E0, N, cursor, csrs, csrd);

    // ---- stream 0: constants + input GEMM ----
    prep_kernel<<<1, 64>>>(att_qp, ent_p, path_p, rot, sum);
    path_precomp_kernel<<<1, 128>>>(po_W, po_b, out_W, out_b, Mp, c0p);
    transpose_kernel<<<(128 * 64 + 255) / 256, 256>>>(W_in, wt0, 128, 64);
    transpose_kernel<<<(128 * 128 + 255) / 256, 256>>>(lin_W, wt1, 128, 128);
    transpose_kernel<<<(128 * 128 + 255) / 256, 256>>>(lin_W + 128 * 128,
                                                       wt1 + 128 * 128, 128, 128);
    {
        dim3 g((N + 63) / 64, 2);
        gemm_tile_kernel<64, true, false><<<g, 256, SMEM_G64>>>(
            x, wt0, b_in, nullptr, nullptr, nullptr, bufA, N);
    }

    float* hcur = bufA;
    float* hnext = bufB;
    for (int l = 0; l < 2; l++) {
        // fork: edge chain on s1 (needs only hcur + csr + rot)
        cudaEventRecord(evF[l], 0);
        cudaStreamWaitEvent(s1, evF[l], 0);
        qk_proj_kernel<<<(N * 32 + 255) / 256, 256, 0, s1>>>(
            hcur, attq_W + l * 4 * 128, attq_b + l * 4,
            attk_W + l * 4 * 128, attk_b + l * 4, qb, kb, N);
        edge_prep_kernel<<<(N + 127) / 128, 128, 0, s1>>>(qb, kb, psi, kcs, N);
        edge_score_kernel<<<(Et + 255) / 256, 256, 0, s1>>>(
            psi, kcs, csrs, csrd, Et, rot + l * 32, att, sum + l);
        cudaEventRecord(evJ[l], s1);

        // stream 0: ent circuit then GEMM with fused z-projection -> xc
        ent_kernel<<<(N + 127) / 128, 128>>>(hcur, rot + 64 + l * 64, zb, N);
        {
            dim3 g((N + 63) / 64, 2);
            gemm_tile_kernel<128, false, true><<<g, 256, SMEM_G128>>>(
                hcur, wt1 + l * 128 * 128, lin_b + l * 128,
                zb, qproj_W + l * 128 * 4, qproj_b + l * 128, xc, N);
        }

        // join, then aggregate
        cudaStreamWaitEvent(0, evJ[l], 0);
        aggregate_kernel<<<(N * 32 + 255) / 256, 256>>>(
            att, sum + l, xc, rowptr, csrs, hnext, N);
        float* t = hcur; hcur = hnext; hnext = t;
    }

    path_proj_kernel<<<(N * 32 + 255) / 256, 256>>>(hcur, pi_W, pi_b, qb, N);
    path_out_kernel<<<(N + 127) / 128, 128>>>(qb, rot + 192, Mp, c0p, out, N);
}

// round 10
// speedup vs baseline: 2.1540x; 1.0895x over previous
#include <cuda_runtime.h>
#include <cuda_bf16.h>
#include <cuda_fp16.h>

#define PI_HALF 1.57079632679489662f
#define NMAX 20000
#define EMAX 300000

// ---------------- scratch (no allocation allowed) ----------------
__device__ float  g_bufA[NMAX * 128];
__device__ float  g_bufB[NMAX * 128];
__device__ __half g_xch[NMAX * 128];     // fp16 x_comb (only consumed by gather)
__device__ float  g_q[NMAX * 4];
__device__ float  g_k[NMAX * 4];
__device__ float  g_z[NMAX * 4];
__device__ float  g_psi[NMAX * 32];      // per-node state after RY(q)+H (16 complex)
__device__ float  g_kcs[NMAX * 8];       // per-node cos/sin of k[i]/2
__device__ float  g_att[EMAX + NMAX];
__device__ float  g_sum[2];
__device__ float  g_rot[36 * 8];         // 36 complex 2x2 matrices
__device__ int    g_deg[NMAX + 1];
__device__ int    g_rowptr[NMAX + 1];
__device__ int    g_cursor[NMAX + 1];
__device__ int    g_csr_src[EMAX + NMAX];
__device__ int    g_csr_dst[EMAX + NMAX];
__device__ float  g_M[32 * 4];
__device__ float  g_c0[32];
__device__ float  g_Wt0[64 * 128];       // W_in^T  [K=64][C=128]
__device__ float  g_Wt1[2 * 128 * 128];  // lin_W^T [K=128][C=128] per layer

// ---------------- complex helpers ----------------
__device__ __forceinline__ float2 cmul(float2 a, float2 b) {
    return make_float2(a.x * b.x - a.y * b.y, a.x * b.y + a.y * b.x);
}

template<int M>
__device__ __forceinline__ void ap_ry(float2* s, float c, float sn) {
#pragma unroll
    for (int i = 0; i < 16; i++) {
        if (i & M) continue;
        float2 a = s[i], b = s[i | M];
        s[i]     = make_float2(c * a.x - sn * b.x, c * a.y - sn * b.y);
        s[i | M] = make_float2(sn * a.x + c * b.x, sn * a.y + c * b.y);
    }
}

template<int M>
__device__ __forceinline__ void ap_h(float2* s) {
    const float r = 0.70710678118654752f;
#pragma unroll
    for (int i = 0; i < 16; i++) {
        if (i & M) continue;
        float2 a = s[i], b = s[i | M];
        s[i]     = make_float2((a.x + b.x) * r, (a.y + b.y) * r);
        s[i | M] = make_float2((a.x - b.x) * r, (a.y - b.y) * r);
    }
}

template<int MC, int MT>
__device__ __forceinline__ void ap_cry(float2* s, float c, float sn) {
#pragma unroll
    for (int i = 0; i < 16; i++) {
        if (!(i & MC) || (i & MT)) continue;
        float2 a = s[i], b = s[i | MT];
        s[i]      = make_float2(c * a.x - sn * b.x, c * a.y - sn * b.y);
        s[i | MT] = make_float2(sn * a.x + c * b.x, sn * a.y + c * b.y);
    }
}

template<int MC, int MT>
__device__ __forceinline__ void ap_cnot(float2* s) {
#pragma unroll
    for (int i = 0; i < 16; i++) {
        if (!(i & MC) || (i & MT)) continue;
        float2 t = s[i];
        s[i] = s[i | MT];
        s[i | MT] = t;
    }
}

template<int M>
__device__ __forceinline__ void ap_rot(float2* s, const float* __restrict__ u) {
    float2 u00 = make_float2(u[0], u[1]);
    float2 u01 = make_float2(u[2], u[3]);
    float2 u10 = make_float2(u[4], u[5]);
    float2 u11 = make_float2(u[6], u[7]);
#pragma unroll
    for (int i = 0; i < 16; i++) {
        if (i & M) continue;
        float2 a = s[i], b = s[i | M];
        float2 ra = cmul(u00, a), rb = cmul(u01, b);
        float2 sa = cmul(u10, a), sb = cmul(u11, b);
        s[i]     = make_float2(ra.x + rb.x, ra.y + rb.y);
        s[i | M] = make_float2(sa.x + sb.x, sa.y + sb.y);
    }
}

__device__ __forceinline__ void init_state(float2* s) {
#pragma unroll
    for (int i = 0; i < 16; i++) s[i] = make_float2(0.f, 0.f);
    s[0] = make_float2(1.f, 0.f);
}

__device__ __forceinline__ void zexp4(const float2* s, float z[4]) {
    z[0] = z[1] = z[2] = z[3] = 0.f;
#pragma unroll
    for (int i = 0; i < 16; i++) {
        float n = s[i].x * s[i].x + s[i].y * s[i].y;
        z[0] += (i & 8) ? -n : n;
        z[1] += (i & 4) ? -n : n;
        z[2] += (i & 2) ? -n : n;
        z[3] += (i & 1) ? -n : n;
    }
}

__device__ __forceinline__ void ry_all(float2* s, const float a[4]) {
    float c, sn;
    __sincosf(a[0] * 0.5f, &sn, &c); ap_ry<8>(s, c, sn);
    __sincosf(a[1] * 0.5f, &sn, &c); ap_ry<4>(s, c, sn);
    __sincosf(a[2] * 0.5f, &sn, &c); ap_ry<2>(s, c, sn);
    __sincosf(a[3] * 0.5f, &sn, &c); ap_ry<1>(s, c, sn);
}

__device__ __forceinline__ void rot_all(float2* s, const float* __restrict__ rm) {
    ap_rot<8>(s, rm);
    ap_rot<4>(s, rm + 8);
    ap_rot<2>(s, rm + 16);
    ap_rot<1>(s, rm + 24);
}

// ---------------- circuits ----------------
__device__ __forceinline__ void entangle_circ(const float xin[4],
                                              const float* __restrict__ rot,
                                              float z[4]) {
    float2 s[16];
    init_state(s);
    ry_all(s, xin);
#pragma unroll
    for (int l = 0; l < 2; l++) {
        ap_cnot<8, 4>(s); ap_cnot<4, 2>(s); ap_cnot<2, 1>(s);
        rot_all(s, rot + l * 32);
        ap_cnot<8, 1>(s);
    }
    zexp4(s, z);
}

__device__ __forceinline__ void path_circ(const float xin[4],
                                          const float* __restrict__ rot,
                                          float z[4]) {
    float2 s[16];
    init_state(s);
    ap_h<8>(s); ap_h<4>(s); ap_h<2>(s); ap_h<1>(s);
    ry_all(s, xin);
#pragma unroll
    for (int l = 0; l < 3; l++) {
        rot_all(s, rot + l * 32);
        ap_cnot<8, 4>(s); ap_cnot<4, 2>(s); ap_cnot<2, 1>(s);
    }
    zexp4(s, z);
}

// ---------------- fused one-shot setup kernel ----------------
// blocks 0..31:    W_in transpose (8192 elems)
// blocks 32..95:   lin_W layer0 transpose (16384)
// blocks 96..159:  lin_W layer1 transpose (16384)
// block 160:       rot matrices + sum zeroing
// block 161:       path epilogue collapse M / c0
__global__ void setup_kernel(const float* __restrict__ W_in,
                             const float* __restrict__ lin_W,
                             const float* __restrict__ attqp,
                             const float* __restrict__ entp,
                             const float* __restrict__ pathp,
                             const float* __restrict__ poW,
                             const float* __restrict__ pob,
                             const float* __restrict__ outW,
                             const float* __restrict__ outb,
                             float* __restrict__ wt0, float* __restrict__ wt1,
                             float* __restrict__ rot, float* __restrict__ sums,
                             float* __restrict__ M, float* __restrict__ c0) {
    int blk = blockIdx.x, tid = threadIdx.x;
    if (blk < 32) {
        int i = blk * 256 + tid;                    // W_in [128][64]
        int c = i >> 6, k = i & 63;
        wt0[k * 128 + c] = W_in[i];
    } else if (blk < 96) {
        int i = (blk - 32) * 256 + tid;             // lin_W[0] [128][128]
        int c = i >> 7, k = i & 127;
        wt1[k * 128 + c] = lin_W[i];
    } else if (blk < 160) {
        int i = (blk - 96) * 256 + tid;             // lin_W[1]
        int c = i >> 7, k = i & 127;
        wt1[128 * 128 + k * 128 + c] = lin_W[128 * 128 + i];
    } else if (blk == 160) {
        if (tid < 2) sums[tid] = 0.f;
        if (tid >= 36) return;
        const float* p;
        if (tid < 8)       p = attqp + tid * 3;
        else if (tid < 24) p = entp + (tid - 8) * 3;
        else               p = pathp + (tid - 24) * 3;
        float phi = p[0], th = p[1], om = p[2];
        float c, s;  sincosf(th * 0.5f, &s, &c);
        float c1, s1, c2, s2;
        sincosf((phi + om) * 0.5f, &s1, &c1);
        sincosf((phi - om) * 0.5f, &s2, &c2);
        float* u = rot + tid * 8;
        u[0] =  c * c1;  u[1] = -c * s1;
        u[2] = -s * c2;  u[3] = -s * s2;
        u[4] =  s * c2;  u[5] = -s * s2;
        u[6] =  c * c1;  u[7] =  c * s1;
    } else {
        if (tid >= 128) return;
        int o = tid >> 2, j = tid & 3;
        float m = 0.f;
        for (int k = 0; k < 128; k++) m += outW[o * 128 + k] * poW[k * 4 + j];
        M[o * 4 + j] = m;
        if (j == 0) {
            float cc = outb[o];
            for (int k = 0; k < 128; k++) cc += outW[o * 128 + k] * pob[k];
            c0[o] = cc;
        }
    }
}

// ---- CSR build (once per launch) ----
__global__ void csr_count_kernel(const int* __restrict__ ei, int E0, int N,
                                 int* __restrict__ cnt) {
    int e = blockIdx.x * blockDim.x + threadIdx.x;
    if (e >= E0 + N) return;
    int d = (e < E0) ? ei[E0 + e] : e - E0;
    atomicAdd(&cnt[d], 1);
}

__global__ void csr_scan_kernel(const int* __restrict__ cnt,
                                int* __restrict__ rowptr, int* __restrict__ cursor,
                                int N) {
    const int IT = (NMAX + 1023) / 1024;   // 20
    __shared__ int wsum[32];
    int tid = threadIdx.x, lane = tid & 31, wid = tid >> 5;
    int base = tid * IT;
    int v[IT];
    int run = 0;
#pragma unroll
    for (int j = 0; j < IT; j++) {
        v[j] = run;
        int i = base + j;
        run += (i < N) ? cnt[i] : 0;
    }
    int s = run;
#pragma unroll
    for (int off = 1; off < 32; off <<= 1) {
        int t = __shfl_up_sync(0xffffffffu, s, off);
        if (lane >= off) s += t;
    }
    if (lane == 31) wsum[wid] = s;
    __syncthreads();
    if (wid == 0) {
        int w = wsum[lane];
        int ws = w;
#pragma unroll
        for (int off = 1; off < 32; off <<= 1) {
            int t = __shfl_up_sync(0xffffffffu, ws, off);
            if (lane >= off) ws += t;
        }
        wsum[lane] = ws - w;   // exclusive
    }
    __syncthreads();
    int offset = wsum[wid] + (s - run);
#pragma unroll
    for (int j = 0; j < IT; j++) {
        int i = base + j;
        if (i <= N) {
            int val = offset + v[j];
            rowptr[i] = val;
            cursor[i] = val;
        }
    }
}

__global__ void csr_fill_kernel(const int* __restrict__ ei, int E0, int N,
                                int* __restrict__ cursor,
                                int* __restrict__ csr_src, int* __restrict__ csr_dst) {
    int e = blockIdx.x * blockDim.x + threadIdx.x;
    if (e >= E0 + N) return;
    int s, d;
    if (e < E0) { s = ei[e]; d = ei[E0 + e]; }
    else        { s = d = e - E0; }
    int p = atomicAdd(&cursor[d], 1);
    csr_src[p] = s;
    csr_dst[p] = d;
}

// ---------------- register-tiled GEMM ----------------
// out = act(in[M][K] @ Wt + b [+ z @ qpW^T + qpb]); HOUT -> fp16 store.
template<int K, bool RELU, bool ZPROJ, bool HOUT>
__global__ void gemm_tile_kernel(const float* __restrict__ in,
                                 const float* __restrict__ Wt,
                                 const float* __restrict__ b,
                                 const float* __restrict__ z,
                                 const float* __restrict__ qpW,
                                 const float* __restrict__ qpb,
                                 float* __restrict__ outf,
                                 __half* __restrict__ outh, int M) {
    extern __shared__ float sm[];
    float* As = sm;             // [64][K]
    float* Bs = sm + 64 * K;    // [K][68]
    int tid = threadIdx.x;
    int r0 = blockIdx.x * 64;
    int c0 = blockIdx.y * 64;
    int nrows = min(64, M - r0);
    for (int idx = tid * 4; idx < 64 * K; idx += 1024) {
        int r = idx / K, k = idx % K;
        float4 v = make_float4(0.f, 0.f, 0.f, 0.f);
        if (r < nrows) v = *(const float4*)(in + (size_t)(r0 + r) * K + k);
        *(float4*)(As + r * K + k) = v;
    }
    for (int idx = tid * 4; idx < K * 64; idx += 1024) {
        int k = idx >> 6, c = idx & 63;
        float4 v = *(const float4*)(Wt + (size_t)k * 128 + c0 + c);
        *(float4*)(Bs + k * 68 + c) = v;
    }
    __syncthreads();
    int tr = (tid >> 4) * 4;
    int tc = (tid & 15) * 4;
    float acc[4][4];
#pragma unroll
    for (int i = 0; i < 4; i++)
#pragma unroll
        for (int j = 0; j < 4; j++) acc[i][j] = 0.f;
#pragma unroll 2
    for (int k = 0; k < K; k += 4) {
        float4 b0 = *(const float4*)(Bs + (k + 0) * 68 + tc);
        float4 b1 = *(const float4*)(Bs + (k + 1) * 68 + tc);
        float4 b2 = *(const float4*)(Bs + (k + 2) * 68 + tc);
        float4 b3 = *(const float4*)(Bs + (k + 3) * 68 + tc);
#pragma unroll
        for (int i = 0; i < 4; i++) {
            float4 a = *(const float4*)(As + (tr + i) * K + k);
            acc[i][0] += a.x * b0.x + a.y * b1.x + a.z * b2.x + a.w * b3.x;
            acc[i][1] += a.x * b0.y + a.y * b1.y + a.z * b2.y + a.w * b3.y;
            acc[i][2] += a.x * b0.z + a.y * b1.z + a.z * b2.z + a.w * b3.z;
            acc[i][3] += a.x * b0.w + a.y * b1.w + a.z * b2.w + a.w * b3.w;
        }
    }
    float4 bias = *(const float4*)(b + c0 + tc);
    float4 qw[4], qbias;
    if (ZPROJ) {
#pragma unroll
        for (int j = 0; j < 4; j++)
            qw[j] = *(const float4*)(qpW + (c0 + tc + j) * 4);
        qbias = *(const float4*)(qpb + c0 + tc);
    }
#pragma unroll
    for (int i = 0; i < 4; i++) {
        int r = r0 + tr + i;
        if (r < M) {
            float4 o;
            o.x = acc[i][0] + bias.x;
            o.y = acc[i][1] + bias.y;
            o.z = acc[i][2] + bias.z;
            o.w = acc[i][3] + bias.w;
            if (ZPROJ) {
                float4 zv = *(const float4*)(z + r * 4);
                o.x += zv.x * qw[0].x + zv.y * qw[0].y + zv.z * qw[0].z + zv.w * qw[0].w + qbias.x;
                o.y += zv.x * qw[1].x + zv.y * qw[1].y + zv.z * qw[1].z + zv.w * qw[1].w + qbias.y;
                o.z += zv.x * qw[2].x + zv.y * qw[2].y + zv.z * qw[2].z + zv.w * qw[2].w + qbias.z;
                o.w += zv.x * qw[3].x + zv.y * qw[3].y + zv.z * qw[3].z + zv.w * qw[3].w + qbias.w;
            }
            if (RELU) {
                o.x = fmaxf(o.x, 0.f); o.y = fmaxf(o.y, 0.f);
                o.z = fmaxf(o.z, 0.f); o.w = fmaxf(o.w, 0.f);
            }
            if (HOUT) {
                __half2 h0 = __floats2half2_rn(o.x, o.y);
                __half2 h1 = __floats2half2_rn(o.z, o.w);
                uint2 u;
                u.x = *reinterpret_cast<unsigned*>(&h0);
                u.y = *reinterpret_cast<unsigned*>(&h1);
                *(uint2*)(outh + (size_t)r * 128 + c0 + tc) = u;
            } else {
                *(float4*)(outf + (size_t)r * 128 + c0 + tc) = o;
            }
        }
    }
}

// ---------------- per-node kernels ----------------
__global__ void ent_kernel(const float* __restrict__ h,
                           const float* __restrict__ entrot,
                           float* __restrict__ z, int N) {
    int n = blockIdx.x * blockDim.x + threadIdx.x;
    if (n >= N) return;
    float4 hv = *(const float4*)(h + n * 128);
    float xin[4] = {tanhf(hv.x) * PI_HALF, tanhf(hv.y) * PI_HALF,
                    tanhf(hv.z) * PI_HALF, tanhf(hv.w) * PI_HALF};
    float zz[4];
    entangle_circ(xin, entrot, zz);
    *(float4*)(z + n * 4) = make_float4(zz[0], zz[1], zz[2], zz[3]);
}

// Warp per node: q/k projections (+tanh) only.
__global__ void qk_proj_kernel(const float* __restrict__ h,
                               const float* __restrict__ attqW, const float* __restrict__ attqb,
                               const float* __restrict__ attkW, const float* __restrict__ attkb,
                               float* __restrict__ qout, float* __restrict__ kout, int N) {
    int gwid = (blockIdx.x * blockDim.x + threadIdx.x) >> 5;
    int lane = threadIdx.x & 31;
    if (gwid >= N) return;
    const float4 hv = *(const float4*)(h + gwid * 128 + lane * 4);
    float acc[8];
#pragma unroll
    for (int j = 0; j < 8; j++) {
        const float* Wr = (j < 4 ? attqW + j * 128 : attkW + (j - 4) * 128) + lane * 4;
        float4 w = *(const float4*)Wr;
        acc[j] = hv.x * w.x + hv.y * w.y + hv.z * w.z + hv.w * w.w;
    }
#pragma unroll
    for (int off = 16; off; off >>= 1)
#pragma unroll
        for (int j = 0; j < 8; j++)
            acc[j] += __shfl_xor_sync(0xffffffffu, acc[j], off);
    if (lane < 4) {
        qout[gwid * 4 + lane] = tanhf(acc[lane] + attqb[lane]) * PI_HALF;
        kout[gwid * 4 + lane] = tanhf(acc[4 + lane] + attkb[lane]) * PI_HALF;
    }
}

// Thread per node: psi = H^4 RY(q)|0>, kcs = (cos,sin)(k_i/2).
__global__ void edge_prep_kernel(const float* __restrict__ q,
                                 const float* __restrict__ k,
                                 float* __restrict__ psi, float* __restrict__ kcs, int N) {
    int n = blockIdx.x * blockDim.x + threadIdx.x;
    if (n >= N) return;
    float4 qa = *(const float4*)(q + n * 4);
    float qq[4] = {qa.x, qa.y, qa.z, qa.w};
    float2 s[16];
    init_state(s);
    ry_all(s, qq);
    ap_h<8>(s); ap_h<4>(s); ap_h<2>(s); ap_h<1>(s);
    float4* po = (float4*)(psi + n * 32);
#pragma unroll
    for (int i = 0; i < 8; i++)
        po[i] = make_float4(s[2 * i].x, s[2 * i].y, s[2 * i + 1].x, s[2 * i + 1].y);
    float4 ka = *(const float4*)(k + n * 4);
    float kk[4] = {ka.x, ka.y, ka.z, ka.w};
    float cs[8];
#pragma unroll
    for (int i = 0; i < 4; i++)
        __sincosf(kk[i] * 0.5f, &cs[2 * i + 1], &cs[2 * i]);
    float4* ko = (float4*)(kcs + n * 8);
    ko[0] = make_float4(cs[0], cs[1], cs[2], cs[3]);
    ko[1] = make_float4(cs[4], cs[5], cs[6], cs[7]);
}

// One thread per CSR entry: CRYs + Rot + weighted |.|^2 + exp.
__global__ void edge_score_kernel(const float* __restrict__ psi,
                                  const float* __restrict__ kcs,
                                  const int* __restrict__ csr_src,
                                  const int* __restrict__ csr_dst, int Et,
                                  const float* __restrict__ attrot,
                                  float* __restrict__ att, float* __restrict__ sumptr) {
    int i = blockIdx.x * blockDim.x + threadIdx.x;
    float es = 0.f;
    if (i < Et) {
        int sN = csr_src[i], dN = csr_dst[i];
        float2 s[16];
        const float4* pp = (const float4*)(psi + sN * 32);
#pragma unroll
        for (int j = 0; j < 8; j++) {
            float4 v = pp[j];
            s[2 * j]     = make_float2(v.x, v.y);
            s[2 * j + 1] = make_float2(v.z, v.w);
        }
        float4 cs0 = *(const float4*)(kcs + dN * 8);
        float4 cs1 = *(const float4*)(kcs + dN * 8 + 4);
        ap_cry<8, 4>(s, cs0.x, cs0.y);
        ap_cry<4, 2>(s, cs0.z, cs0.w);
        ap_cry<2, 1>(s, cs1.x, cs1.y);
        ap_cry<1, 8>(s, cs1.z, cs1.w);
        rot_all(s, attrot);
        float score = 0.f;
#pragma unroll
        for (int j = 0; j < 16; j++) {
            float n = s[j].x * s[j].x + s[j].y * s[j].y;
            score += n * (1.0f - 0.5f * (float)__popc(j));
        }
        es = expf(score);
        att[i] = es;
    }
    float v = es;
#pragma unroll
    for (int off = 16; off; off >>= 1) v += __shfl_xor_sync(0xffffffffu, v, off);
    __shared__ float sred[8];
    int lane = threadIdx.x & 31, warp = threadIdx.x >> 5;
    if (lane == 0) sred[warp] = v;
    __syncthreads();
    if (threadIdx.x == 0) {
        float t = 0.f;
#pragma unroll
        for (int j = 0; j < 8; j++) t += sred[j];
        atomicAdd(sumptr, t);
    }
}

__device__ __forceinline__ float4 ld_half4(const __half* p) {
    uint2 u = *(const uint2*)p;
    __half2 a = *reinterpret_cast<__half2*>(&u.x);
    __half2 b = *reinterpret_cast<__half2*>(&u.y);
    float2 fa = __half22float2(a), fb = __half22float2(b);
    return make_float4(fa.x, fa.y, fb.x, fb.y);
}

// Warp per node: atomic-free fp16 CSR gather + fused ReLU, 4-deep pipelined.
__global__ void aggregate_kernel(const float* __restrict__ att,
                                 const float* __restrict__ sumptr,
                                 const __half* __restrict__ xc,
                                 const int* __restrict__ rowptr,
                                 const int* __restrict__ csr_src,
                                 float* __restrict__ hn, int N) {
    int n = (blockIdx.x * blockDim.x + threadIdx.x) >> 5;
    int lane = threadIdx.x & 31;
    if (n >= N) return;
    int beg = rowptr[n], end = rowptr[n + 1];
    float4 acc = make_float4(0.f, 0.f, 0.f, 0.f);
    int i = beg;
    for (; i + 4 <= end; i += 4) {
        int s0 = csr_src[i],     s1 = csr_src[i + 1];
        int s2 = csr_src[i + 2], s3 = csr_src[i + 3];
        float w0 = att[i],     w1 = att[i + 1];
        float w2 = att[i + 2], w3 = att[i + 3];
        float4 v0 = ld_half4(xc + s0 * 128 + lane * 4);
        float4 v1 = ld_half4(xc + s1 * 128 + lane * 4);
        float4 v2 = ld_half4(xc + s2 * 128 + lane * 4);
        float4 v3 = ld_half4(xc + s3 * 128 + lane * 4);
        acc.x += w0 * v0.x + w1 * v1.x + w2 * v2.x + w3 * v3.x;
        acc.y += w0 * v0.y + w1 * v1.y + w2 * v2.y + w3 * v3.y;
        acc.z += w0 * v0.z + w1 * v1.z + w2 * v2.z + w3 * v3.z;
        acc.w += w0 * v0.w + w1 * v1.w + w2 * v2.w + w3 * v3.w;
    }
    for (; i < end; i++) {
        int s = csr_src[i];
        float w = att[i];
        float4 v = ld_half4(xc + s * 128 + lane * 4);
        acc.x += w * v.x; acc.y += w * v.y; acc.z += w * v.z; acc.w += w * v.w;
    }
    float inv = 1.0f / sumptr[0];
    acc.x = fmaxf(acc.x * inv, 0.f); acc.y = fmaxf(acc.y * inv, 0.f);
    acc.z = fmaxf(acc.z * inv, 0.f); acc.w = fmaxf(acc.w * inv, 0.f);
    *(float4*)(hn + n * 128 + lane * 4) = acc;
}

// Warp per node: pq projection only.
__global__ void path_proj_kernel(const float* __restrict__ h,
                                 const float* __restrict__ piW, const float* __restrict__ pib,
                                 float* __restrict__ pq, int N) {
    int n = (blockIdx.x * blockDim.x + threadIdx.x) >> 5;
    int lane = threadIdx.x & 31;
    if (n >= N) return;
    float4 hv = *(const float4*)(h + n * 128 + lane * 4);
    float acc[4];
#pragma unroll
    for (int j = 0; j < 4; j++) {
        float4 w = *(const float4*)(piW + j * 128 + lane * 4);
        acc[j] = hv.x * w.x + hv.y * w.y + hv.z * w.z + hv.w * w.w;
    }
#pragma unroll
    for (int off = 16; off; off >>= 1)
#pragma unroll
        for (int j = 0; j < 4; j++)
            acc[j] += __shfl_xor_sync(0xffffffffu, acc[j], off);
    if (lane < 4)
        pq[n * 4 + lane] = tanhf(acc[lane] + pib[lane]) * PI_HALF;
}

// Thread per node: path circuit + collapsed epilogue out = c0 + M @ z.
__global__ void path_out_kernel(const float* __restrict__ pq,
                                const float* __restrict__ pathrot,
                                const float* __restrict__ M, const float* __restrict__ c0,
                                float* __restrict__ out, int N) {
    int n = blockIdx.x * blockDim.x + threadIdx.x;
    if (n >= N) return;
    float4 p = *(const float4*)(pq + n * 4);
    float xin[4] = {p.x, p.y, p.z, p.w};
    float z[4];
    path_circ(xin, pathrot, z);
    float4* o4 = (float4*)(out + n * 32);
#pragma unroll
    for (int g = 0; g < 8; g++) {
        float4 r;
        float* rp = (float*)&r;
#pragma unroll
        for (int i = 0; i < 4; i++) {
            int o = g * 4 + i;
            float4 m = *(const float4*)(M + o * 4);
            rp[i] = c0[o] + z[0] * m.x + z[1] * m.y + z[2] * m.z + z[3] * m.w;
        }
        o4[g] = r;
    }
}

// ---------------- host ----------------
extern "C" void kernel_launch(void* const* d_in, const int* in_sizes, int n_in,
                              void* d_out, int out_size) {
    const float* x        = (const float*)d_in[0];
    const float* W_in     = (const float*)d_in[1];
    const float* b_in     = (const float*)d_in[2];
    const float* lin_W    = (const float*)d_in[3];
    const float* lin_b    = (const float*)d_in[4];
    const float* qproj_W  = (const float*)d_in[5];
    const float* qproj_b  = (const float*)d_in[6];
    const float* ent_p    = (const float*)d_in[7];
    const float* attq_W   = (const float*)d_in[8];
    const float* attq_b   = (const float*)d_in[9];
    const float* attk_W   = (const float*)d_in[10];
    const float* attk_b   = (const float*)d_in[11];
    const float* att_qp   = (const float*)d_in[12];
    const float* path_p   = (const float*)d_in[13];
    const float* pi_W     = (const float*)d_in[14];
    const float* pi_b     = (const float*)d_in[15];
    const float* po_W     = (const float*)d_in[16];
    const float* po_b     = (const float*)d_in[17];
    const float* out_W    = (const float*)d_in[18];
    const float* out_b    = (const float*)d_in[19];
    const int*   ei       = (const int*)d_in[20];
    float* out = (float*)d_out;

    int N  = in_sizes[0] / 64;
    int E0 = in_sizes[20] / 2;
    int Et = E0 + N;

    float *bufA, *bufB, *qb, *kb, *zb, *psi, *kcs, *att, *sum, *rot, *Mp, *c0p;
    float *wt0, *wt1;
    __half* xch;
    int *deg, *rowptr, *cursor, *csrs, *csrd;
    cudaGetSymbolAddress((void**)&bufA,   g_bufA);
    cudaGetSymbolAddress((void**)&bufB,   g_bufB);
    cudaGetSymbolAddress((void**)&xch,    g_xch);
    cudaGetSymbolAddress((void**)&qb,     g_q);
    cudaGetSymbolAddress((void**)&kb,     g_k);
    cudaGetSymbolAddress((void**)&zb,     g_z);
    cudaGetSymbolAddress((void**)&psi,    g_psi);
    cudaGetSymbolAddress((void**)&kcs,    g_kcs);
    cudaGetSymbolAddress((void**)&att,    g_att);
    cudaGetSymbolAddress((void**)&sum,    g_sum);
    cudaGetSymbolAddress((void**)&rot,    g_rot);
    cudaGetSymbolAddress((void**)&deg,    g_deg);
    cudaGetSymbolAddress((void**)&rowptr, g_rowptr);
    cudaGetSymbolAddress((void**)&cursor, g_cursor);
    cudaGetSymbolAddress((void**)&csrs,   g_csr_src);
    cudaGetSymbolAddress((void**)&csrd,   g_csr_dst);
    cudaGetSymbolAddress((void**)&Mp,     g_M);
    cudaGetSymbolAddress((void**)&c0p,    g_c0);
    cudaGetSymbolAddress((void**)&wt0,    g_Wt0);
    cudaGetSymbolAddress((void**)&wt1,    g_Wt1);

    // one-time stream/event setup (host resources, not device memory)
    static cudaStream_t s1 = nullptr;
    static cudaEvent_t evFork = nullptr, evF[2], evJ[2];
    if (!s1) {
        cudaStreamCreateWithFlags(&s1, cudaStreamNonBlocking);
        cudaEventCreateWithFlags(&evFork, cudaEventDisableTiming);
        for (int i = 0; i < 2; i++) {
            cudaEventCreateWithFlags(&evF[i], cudaEventDisableTiming);
            cudaEventCreateWithFlags(&evJ[i], cudaEventDisableTiming);
        }
    }

    const int SMEM_G64  = (64 * 64 + 64 * 68) * 4;    // 33792
    const int SMEM_G128 = (64 * 128 + 128 * 68) * 4;  // 67584
    cudaFuncSetAttribute(gemm_tile_kernel<64, true, false, false>,
                         cudaFuncAttributeMaxDynamicSharedMemorySize, SMEM_G64);
    cudaFuncSetAttribute(gemm_tile_kernel<128, false, true, true>,
                         cudaFuncAttributeMaxDynamicSharedMemorySize, SMEM_G128);

    // ---- fork s1: CSR build overlaps setup + input GEMM ----
    cudaEventRecord(evFork, 0);
    cudaStreamWaitEvent(s1, evFork, 0);
    cudaMemsetAsync(deg, 0, (size_t)(N + 1) * sizeof(int), s1);
    csr_count_kernel<<<(Et + 255) / 256, 256, 0, s1>>>(ei, E0, N, deg);
    csr_scan_kernel<<<1, 1024, 0, s1>>>(deg, rowptr, cursor, N);
    csr_fill_kernel<<<(Et + 255) / 256, 256, 0, s1>>>(ei, E0, N, cursor, csrs, csrd);

    // ---- stream 0: one fused setup launch + input GEMM ----
    setup_kernel<<<162, 256>>>(W_in, lin_W, att_qp, ent_p, path_p,
                               po_W, po_b, out_W, out_b,
                               wt0, wt1, rot, sum, Mp, c0p);
    {
        dim3 g((N + 63) / 64, 2);
        gemm_tile_kernel<64, true, false, false><<<g, 256, SMEM_G64>>>(
            x, wt0, b_in, nullptr, nullptr, nullptr, bufA, nullptr, N);
    }

    float* hcur = bufA;
    float* hnext = bufB;
    for (int l = 0; l < 2; l++) {
        // fork: edge chain on s1 (needs only hcur + csr + rot)
        cudaEventRecord(evF[l], 0);
        cudaStreamWaitEvent(s1, evF[l], 0);
        qk_proj_kernel<<<(N * 32 + 255) / 256, 256, 0, s1>>>(
            hcur, attq_W + l * 4 * 128, attq_b + l * 4,
            attk_W + l * 4 * 128, attk_b + l * 4, qb, kb, N);
        edge_prep_kernel<<<(N + 127) / 128, 128, 0, s1>>>(qb, kb, psi, kcs, N);
        edge_score_kernel<<<(Et + 255) / 256, 256, 0, s1>>>(
            psi, kcs, csrs, csrd, Et, rot + l * 32, att, sum + l);
        cudaEventRecord(evJ[l], s1);

        // stream 0: ent circuit then GEMM with fused z-projection -> fp16 xc
        ent_kernel<<<(N + 127) / 128, 128>>>(hcur, rot + 64 + l * 64, zb, N);
        {
            dim3 g((N + 63) / 64, 2);
            gemm_tile_kernel<128, false, true, true><<<g, 256, SMEM_G128>>>(
                hcur, wt1 + l * 128 * 128, lin_b + l * 128,
                zb, qproj_W + l * 128 * 4, qproj_b + l * 128, nullptr, xch, N);
        }

        // join, then aggregate
        cudaStreamWaitEvent(0, evJ[l], 0);
        aggregate_kernel<<<(N * 32 + 255) / 256, 256>>>(
            att, sum + l, xch, rowptr, csrs, hnext, N);
        float* t = hcur; hcur = hnext; hnext = t;
    }

    path_proj_kernel<<<(N * 32 + 255) / 256, 256>>>(hcur, pi_W, pi_b, qb, N);
    path_out_kernel<<<(N + 127) / 128, 128>>>(qb, rot + 192, Mp, c0p, out, N);
}

// round 14
// speedup vs baseline: 2.3630x; 1.0970x over previous
#include <cuda_runtime.h>
#include <cuda_bf16.h>
#include <cuda_fp16.h>

#define PI_HALF 1.57079632679489662f
#define NMAX 20000
#define EMAX 300000

// ---------------- scratch (no allocation allowed) ----------------
__device__ float  g_bufA[NMAX * 128];
__device__ float  g_bufB[NMAX * 128];
__device__ __half g_xch[NMAX * 128];     // fp16 x_comb (only consumed by gather)
__device__ float  g_q[NMAX * 4];
__device__ float  g_k[NMAX * 4];
__device__ float  g_z[NMAX * 4];
__device__ float  g_psi[NMAX * 32];      // per-node state after RY(q)+H (16 complex)
__device__ float  g_kcs[NMAX * 8];       // per-node cos/sin of k[i]/2
__device__ float  g_att[EMAX + NMAX];
__device__ float  g_sum[2];
__device__ float  g_rot[36 * 8];         // 36 complex 2x2 matrices
__device__ float  g_attM[2 * 4 * 4];     // per layer, per qubit: {a, br, bi, pad}
__device__ int    g_deg[NMAX + 1];
__device__ int    g_rowptr[NMAX + 1];
__device__ int    g_cursor[NMAX + 1];
__device__ int    g_csr_src[EMAX + NMAX];
__device__ int    g_csr_dst[EMAX + NMAX];
__device__ float  g_M[32 * 4];
__device__ float  g_c0[32];
__device__ float  g_Wt0[64 * 128];       // W_in^T  [K=64][C=128]
__device__ float  g_Wt1[2 * 128 * 128];  // lin_W^T [K=128][C=128] per layer

// ---------------- complex helpers ----------------
__device__ __forceinline__ float2 cmul(float2 a, float2 b) {
    return make_float2(a.x * b.x - a.y * b.y, a.x * b.y + a.y * b.x);
}

template<int M>
__device__ __forceinline__ void ap_ry(float2* s, float c, float sn) {
#pragma unroll
    for (int i = 0; i < 16; i++) {
        if (i & M) continue;
        float2 a = s[i], b = s[i | M];
        s[i]     = make_float2(c * a.x - sn * b.x, c * a.y - sn * b.y);
        s[i | M] = make_float2(sn * a.x + c * b.x, sn * a.y + c * b.y);
    }
}

template<int M>
__device__ __forceinline__ void ap_h(float2* s) {
    const float r = 0.70710678118654752f;
#pragma unroll
    for (int i = 0; i < 16; i++) {
        if (i & M) continue;
        float2 a = s[i], b = s[i | M];
        s[i]     = make_float2((a.x + b.x) * r, (a.y + b.y) * r);
        s[i | M] = make_float2((a.x - b.x) * r, (a.y - b.y) * r);
    }
}

template<int MC, int MT>
__device__ __forceinline__ void ap_cry(float2* s, float c, float sn) {
#pragma unroll
    for (int i = 0; i < 16; i++) {
        if (!(i & MC) || (i & MT)) continue;
        float2 a = s[i], b = s[i | MT];
        s[i]      = make_float2(c * a.x - sn * b.x, c * a.y - sn * b.y);
        s[i | MT] = make_float2(sn * a.x + c * b.x, sn * a.y + c * b.y);
    }
}

template<int MC, int MT>
__device__ __forceinline__ void ap_cnot(float2* s) {
#pragma unroll
    for (int i = 0; i < 16; i++) {
        if (!(i & MC) || (i & MT)) continue;
        float2 t = s[i];
        s[i] = s[i | MT];
        s[i | MT] = t;
    }
}

template<int M>
__device__ __forceinline__ void ap_rot(float2* s, const float* __restrict__ u) {
    float2 u00 = make_float2(u[0], u[1]);
    float2 u01 = make_float2(u[2], u[3]);
    float2 u10 = make_float2(u[4], u[5]);
    float2 u11 = make_float2(u[6], u[7]);
#pragma unroll
    for (int i = 0; i < 16; i++) {
        if (i & M) continue;
        float2 a = s[i], b = s[i | M];
        float2 ra = cmul(u00, a), rb = cmul(u01, b);
        float2 sa = cmul(u10, a), sb = cmul(u11, b);
        s[i]     = make_float2(ra.x + rb.x, ra.y + rb.y);
        s[i | M] = make_float2(sa.x + sb.x, sa.y + sb.y);
    }
}

__device__ __forceinline__ void init_state(float2* s) {
#pragma unroll
    for (int i = 0; i < 16; i++) s[i] = make_float2(0.f, 0.f);
    s[0] = make_float2(1.f, 0.f);
}

__device__ __forceinline__ void zexp4(const float2* s, float z[4]) {
    z[0] = z[1] = z[2] = z[3] = 0.f;
#pragma unroll
    for (int i = 0; i < 16; i++) {
        float n = s[i].x * s[i].x + s[i].y * s[i].y;
        z[0] += (i & 8) ? -n : n;
        z[1] += (i & 4) ? -n : n;
        z[2] += (i & 2) ? -n : n;
        z[3] += (i & 1) ? -n : n;
    }
}

__device__ __forceinline__ void ry_all(float2* s, const float a[4]) {
    float c, sn;
    __sincosf(a[0] * 0.5f, &sn, &c); ap_ry<8>(s, c, sn);
    __sincosf(a[1] * 0.5f, &sn, &c); ap_ry<4>(s, c, sn);
    __sincosf(a[2] * 0.5f, &sn, &c); ap_ry<2>(s, c, sn);
    __sincosf(a[3] * 0.5f, &sn, &c); ap_ry<1>(s, c, sn);
}

__device__ __forceinline__ void rot_all(float2* s, const float* __restrict__ rm) {
    ap_rot<8>(s, rm);
    ap_rot<4>(s, rm + 8);
    ap_rot<2>(s, rm + 16);
    ap_rot<1>(s, rm + 24);
}

// ---------------- circuits ----------------
__device__ __forceinline__ void entangle_circ(const float xin[4],
                                              const float* __restrict__ rot,
                                              float z[4]) {
    float2 s[16];
    init_state(s);
    ry_all(s, xin);
#pragma unroll
    for (int l = 0; l < 2; l++) {
        ap_cnot<8, 4>(s); ap_cnot<4, 2>(s); ap_cnot<2, 1>(s);
        rot_all(s, rot + l * 32);
        ap_cnot<8, 1>(s);
    }
    zexp4(s, z);
}

__device__ __forceinline__ void path_circ(const float xin[4],
                                          const float* __restrict__ rot,
                                          float z[4]) {
    float2 s[16];
    init_state(s);
    ap_h<8>(s); ap_h<4>(s); ap_h<2>(s); ap_h<1>(s);
    ry_all(s, xin);
#pragma unroll
    for (int l = 0; l < 3; l++) {
        rot_all(s, rot + l * 32);
        ap_cnot<8, 4>(s); ap_cnot<4, 2>(s); ap_cnot<2, 1>(s);
    }
    zexp4(s, z);
}

// Per-qubit pair sums for observable folding.
// zd = sum (n_p - n_q); R = sum Re(phi_p* phi_q); I = sum Im(phi_p* phi_q).
template<int M>
__device__ __forceinline__ void pair_sums(const float2* s, const float* n,
                                          float& zd, float& R, float& I) {
    zd = 0.f; R = 0.f; I = 0.f;
#pragma unroll
    for (int p = 0; p < 16; p++) {
        if (p & M) continue;
        int q = p | M;
        zd += n[p] - n[q];
        R += s[p].x * s[q].x + s[p].y * s[q].y;
        I += s[p].x * s[q].y - s[p].y * s[q].x;
    }
}

// ---------------- fused one-shot setup kernel ----------------
// blocks 0..31:    W_in transpose (8192 elems)
// blocks 32..95:   lin_W layer0 transpose (16384)
// blocks 96..159:  lin_W layer1 transpose (16384)
// block 160:       rot matrices + att observables + sum zeroing
// block 161:       path epilogue collapse M / c0 (warp-parallel dots)
__global__ void setup_kernel(const float* __restrict__ W_in,
                             const float* __restrict__ lin_W,
                             const float* __restrict__ attqp,
                             const float* __restrict__ entp,
                             const float* __restrict__ pathp,
                             const float* __restrict__ poW,
                             const float* __restrict__ pob,
                             const float* __restrict__ outW,
                             const float* __restrict__ outb,
                             float* __restrict__ wt0, float* __restrict__ wt1,
                             float* __restrict__ rot, float* __restrict__ attM,
                             float* __restrict__ sums,
                             float* __restrict__ M, float* __restrict__ c0) {
    int blk = blockIdx.x, tid = threadIdx.x;
    if (blk < 32) {
        int i = blk * 256 + tid;                    // W_in [128][64]
        int c = i >> 6, k = i & 63;
        wt0[k * 128 + c] = W_in[i];
    } else if (blk < 96) {
        int i = (blk - 32) * 256 + tid;             // lin_W[0] [128][128]
        int c = i >> 7, k = i & 127;
        wt1[k * 128 + c] = lin_W[i];
    } else if (blk < 160) {
        int i = (blk - 96) * 256 + tid;             // lin_W[1]
        int c = i >> 7, k = i & 127;
        wt1[128 * 128 + k * 128 + c] = lin_W[128 * 128 + i];
    } else if (blk == 160) {
        if (tid < 2) sums[tid] = 0.f;
        if (tid >= 36) return;
        const float* p;
        if (tid < 8)       p = attqp + tid * 3;
        else if (tid < 24) p = entp + (tid - 8) * 3;
        else               p = pathp + (tid - 24) * 3;
        float phi = p[0], th = p[1], om = p[2];
        float c, s;  __sincosf(th * 0.5f, &s, &c);
        float c1, s1, c2, s2;
        __sincosf((phi + om) * 0.5f, &s1, &c1);
        __sincosf((phi - om) * 0.5f, &s2, &c2);
        float* u = rot + tid * 8;
        u[0] =  c * c1;  u[1] = -c * s1;
        u[2] = -s * c2;  u[3] = -s * s2;
        u[4] =  s * c2;  u[5] = -s * s2;
        u[6] =  c * c1;  u[7] =  c * s1;
        if (tid < 8) {
            // observable M = Rot^dag Z Rot = [[a, b],[b*, -a]]
            float a  = (u[0] * u[0] + u[1] * u[1]) - (u[4] * u[4] + u[5] * u[5]);
            float br = (u[0] * u[2] + u[1] * u[3]) - (u[4] * u[6] + u[5] * u[7]);
            float bi = (u[0] * u[3] - u[1] * u[2]) - (u[4] * u[7] - u[5] * u[6]);
            float* m = attM + tid * 4;
            m[0] = a; m[1] = br; m[2] = bi; m[3] = 0.f;
        }
    } else {
        // warp w handles outputs o = w*4 .. w*4+3; lanes stride k (coalesced)
        int w = tid >> 5, lane = tid & 31;
#pragma unroll
        for (int oo = 0; oo < 4; oo++) {
            int o = w * 4 + oo;
            float m0 = 0.f, m1 = 0.f, m2 = 0.f, m3 = 0.f, cc = 0.f;
            for (int k = lane; k < 128; k += 32) {
                float wv = outW[o * 128 + k];
                float4 pw = *(const float4*)(poW + k * 4);
                m0 += wv * pw.x; m1 += wv * pw.y;
                m2 += wv * pw.z; m3 += wv * pw.w;
                cc += wv * pob[k];
            }
#pragma unroll
            for (int off = 16; off; off >>= 1) {
                m0 += __shfl_xor_sync(0xffffffffu, m0, off);
                m1 += __shfl_xor_sync(0xffffffffu, m1, off);
                m2 += __shfl_xor_sync(0xffffffffu, m2, off);
                m3 += __shfl_xor_sync(0xffffffffu, m3, off);
                cc += __shfl_xor_sync(0xffffffffu, cc, off);
            }
            if (lane == 0) {
                M[o * 4 + 0] = m0; M[o * 4 + 1] = m1;
                M[o * 4 + 2] = m2; M[o * 4 + 3] = m3;
                c0[o] = cc + outb[o];
            }
        }
    }
}

// ---- CSR build (once per launch) ----
__global__ void csr_count_kernel(const int* __restrict__ ei, int E0, int N,
                                 int* __restrict__ cnt) {
    int e = blockIdx.x * blockDim.x + threadIdx.x;
    if (e >= E0 + N) return;
    int d = (e < E0) ? ei[E0 + e] : e - E0;
    atomicAdd(&cnt[d], 1);
}

__global__ void csr_scan_kernel(const int* __restrict__ cnt,
                                int* __restrict__ rowptr, int* __restrict__ cursor,
                                int N) {
    const int IT = (NMAX + 1023) / 1024;   // 20
    __shared__ int wsum[32];
    int tid = threadIdx.x, lane = tid & 31, wid = tid >> 5;
    int base = tid * IT;
    int v[IT];
    int run = 0;
#pragma unroll
    for (int j = 0; j < IT; j++) {
        v[j] = run;
        int i = base + j;
        run += (i < N) ? cnt[i] : 0;
    }
    int s = run;
#pragma unroll
    for (int off = 1; off < 32; off <<= 1) {
        int t = __shfl_up_sync(0xffffffffu, s, off);
        if (lane >= off) s += t;
    }
    if (lane == 31) wsum[wid] = s;
    __syncthreads();
    if (wid == 0) {
        int w = wsum[lane];
        int ws = w;
#pragma unroll
        for (int off = 1; off < 32; off <<= 1) {
            int t = __shfl_up_sync(0xffffffffu, ws, off);
            if (lane >= off) ws += t;
        }
        wsum[lane] = ws - w;   // exclusive
    }
    __syncthreads();
    int offset = wsum[wid] + (s - run);
#pragma unroll
    for (int j = 0; j < IT; j++) {
        int i = base + j;
        if (i <= N) {
            int val = offset + v[j];
            rowptr[i] = val;
            cursor[i] = val;
        }
    }
}

__global__ void csr_fill_kernel(const int* __restrict__ ei, int E0, int N,
                                int* __restrict__ cursor,
                                int* __restrict__ csr_src, int* __restrict__ csr_dst) {
    int e = blockIdx.x * blockDim.x + threadIdx.x;
    if (e >= E0 + N) return;
    int s, d;
    if (e < E0) { s = ei[e]; d = ei[E0 + e]; }
    else        { s = d = e - E0; }
    int p = atomicAdd(&cursor[d], 1);
    csr_src[p] = s;
    csr_dst[p] = d;
}

// ---------------- register-tiled GEMM ----------------
template<int K, bool RELU, bool ZPROJ, bool HOUT>
__global__ void gemm_tile_kernel(const float* __restrict__ in,
                                 const float* __restrict__ Wt,
                                 const float* __restrict__ b,
                                 const float* __restrict__ z,
                                 const float* __restrict__ qpW,
                                 const float* __restrict__ qpb,
                                 float* __restrict__ outf,
                                 __half* __restrict__ outh, int M) {
    extern __shared__ float sm[];
    float* As = sm;             // [64][K]
    float* Bs = sm + 64 * K;    // [K][68]
    int tid = threadIdx.x;
    int r0 = blockIdx.x * 64;
    int c0 = blockIdx.y * 64;
    int nrows = min(64, M - r0);
    for (int idx = tid * 4; idx < 64 * K; idx += 1024) {
        int r = idx / K, k = idx % K;
        float4 v = make_float4(0.f, 0.f, 0.f, 0.f);
        if (r < nrows) v = *(const float4*)(in + (size_t)(r0 + r) * K + k);
        *(float4*)(As + r * K + k) = v;
    }
    for (int idx = tid * 4; idx < K * 64; idx += 1024) {
        int k = idx >> 6, c = idx & 63;
        float4 v = *(const float4*)(Wt + (size_t)k * 128 + c0 + c);
        *(float4*)(Bs + k * 68 + c) = v;
    }
    __syncthreads();
    int tr = (tid >> 4) * 4;
    int tc = (tid & 15) * 4;
    float acc[4][4];
#pragma unroll
    for (int i = 0; i < 4; i++)
#pragma unroll
        for (int j = 0; j < 4; j++) acc[i][j] = 0.f;
#pragma unroll 2
    for (int k = 0; k < K; k += 4) {
        float4 b0 = *(const float4*)(Bs + (k + 0) * 68 + tc);
        float4 b1 = *(const float4*)(Bs + (k + 1) * 68 + tc);
        float4 b2 = *(const float4*)(Bs + (k + 2) * 68 + tc);
        float4 b3 = *(const float4*)(Bs + (k + 3) * 68 + tc);
#pragma unroll
        for (int i = 0; i < 4; i++) {
            float4 a = *(const float4*)(As + (tr + i) * K + k);
            acc[i][0] += a.x * b0.x + a.y * b1.x + a.z * b2.x + a.w * b3.x;
            acc[i][1] += a.x * b0.y + a.y * b1.y + a.z * b2.y + a.w * b3.y;
            acc[i][2] += a.x * b0.z + a.y * b1.z + a.z * b2.z + a.w * b3.z;
            acc[i][3] += a.x * b0.w + a.y * b1.w + a.z * b2.w + a.w * b3.w;
        }
    }
    float4 bias = *(const float4*)(b + c0 + tc);
    float4 qw[4], qbias;
    if (ZPROJ) {
#pragma unroll
        for (int j = 0; j < 4; j++)
            qw[j] = *(const float4*)(qpW + (c0 + tc + j) * 4);
        qbias = *(const float4*)(qpb + c0 + tc);
    }
#pragma unroll
    for (int i = 0; i < 4; i++) {
        int r = r0 + tr + i;
        if (r < M) {
            float4 o;
            o.x = acc[i][0] + bias.x;
            o.y = acc[i][1] + bias.y;
            o.z = acc[i][2] + bias.z;
            o.w = acc[i][3] + bias.w;
            if (ZPROJ) {
                float4 zv = *(const float4*)(z + r * 4);
                o.x += zv.x * qw[0].x + zv.y * qw[0].y + zv.z * qw[0].z + zv.w * qw[0].w + qbias.x;
                o.y += zv.x * qw[1].x + zv.y * qw[1].y + zv.z * qw[1].z + zv.w * qw[1].w + qbias.y;
                o.z += zv.x * qw[2].x + zv.y * qw[2].y + zv.z * qw[2].z + zv.w * qw[2].w + qbias.z;
                o.w += zv.x * qw[3].x + zv.y * qw[3].y + zv.z * qw[3].z + zv.w * qw[3].w + qbias.w;
            }
            if (RELU) {
                o.x = fmaxf(o.x, 0.f); o.y = fmaxf(o.y, 0.f);
                o.z = fmaxf(o.z, 0.f); o.w = fmaxf(o.w, 0.f);
            }
            if (HOUT) {
                __half2 h0 = __floats2half2_rn(o.x, o.y);
                __half2 h1 = __floats2half2_rn(o.z, o.w);
                uint2 u;
                u.x = *reinterpret_cast<unsigned*>(&h0);
                u.y = *reinterpret_cast<unsigned*>(&h1);
                *(uint2*)(outh + (size_t)r * 128 + c0 + tc) = u;
            } else {
                *(float4*)(outf + (size_t)r * 128 + c0 + tc) = o;
            }
        }
    }
}

// ---------------- per-node kernels ----------------
__global__ void ent_kernel(const float* __restrict__ h,
                           const float* __restrict__ entrot,
                           float* __restrict__ z, int N) {
    int n = blockIdx.x * blockDim.x + threadIdx.x;
    if (n >= N) return;
    float4 hv = *(const float4*)(h + n * 128);
    float xin[4] = {tanhf(hv.x) * PI_HALF, tanhf(hv.y) * PI_HALF,
                    tanhf(hv.z) * PI_HALF, tanhf(hv.w) * PI_HALF};
    float zz[4];
    entangle_circ(xin, entrot, zz);
    *(float4*)(z + n * 4) = make_float4(zz[0], zz[1], zz[2], zz[3]);
}

// Warp per node: q/k projections (+tanh) only.
__global__ void qk_proj_kernel(const float* __restrict__ h,
                               const float* __restrict__ attqW, const float* __restrict__ attqb,
                               const float* __restrict__ attkW, const float* __restrict__ attkb,
                               float* __restrict__ qout, float* __restrict__ kout, int N) {
    int gwid = (blockIdx.x * blockDim.x + threadIdx.x) >> 5;
    int lane = threadIdx.x & 31;
    if (gwid >= N) return;
    const float4 hv = *(const float4*)(h + gwid * 128 + lane * 4);
    float acc[8];
#pragma unroll
    for (int j = 0; j < 8; j++) {
        const float* Wr = (j < 4 ? attqW + j * 128 : attkW + (j - 4) * 128) + lane * 4;
        float4 w = *(const float4*)Wr;
        acc[j] = hv.x * w.x + hv.y * w.y + hv.z * w.z + hv.w * w.w;
    }
#pragma unroll
    for (int off = 16; off; off >>= 1)
#pragma unroll
        for (int j = 0; j < 8; j++)
            acc[j] += __shfl_xor_sync(0xffffffffu, acc[j], off);
    if (lane < 4) {
        qout[gwid * 4 + lane] = tanhf(acc[lane] + attqb[lane]) * PI_HALF;
        kout[gwid * 4 + lane] = tanhf(acc[4 + lane] + attkb[lane]) * PI_HALF;
    }
}

// Thread per node: psi = H^4 RY(q)|0>, kcs = (cos,sin)(k_i/2).
__global__ void edge_prep_kernel(const float* __restrict__ q,
                                 const float* __restrict__ k,
                                 float* __restrict__ psi, float* __restrict__ kcs, int N) {
    int n = blockIdx.x * blockDim.x + threadIdx.x;
    if (n >= N) return;
    float4 qa = *(const float4*)(q + n * 4);
    float qq[4] = {qa.x, qa.y, qa.z, qa.w};
    float2 s[16];
    init_state(s);
    ry_all(s, qq);
    ap_h<8>(s); ap_h<4>(s); ap_h<2>(s); ap_h<1>(s);
    float4* po = (float4*)(psi + n * 32);
#pragma unroll
    for (int i = 0; i < 8; i++)
        po[i] = make_float4(s[2 * i].x, s[2 * i].y, s[2 * i + 1].x, s[2 * i + 1].y);
    float4 ka = *(const float4*)(k + n * 4);
    float kk[4] = {ka.x, ka.y, ka.z, ka.w};
    float cs[8];
#pragma unroll
    for (int i = 0; i < 4; i++)
        __sincosf(kk[i] * 0.5f, &cs[2 * i + 1], &cs[2 * i]);
    float4* ko = (float4*)(kcs + n * 8);
    ko[0] = make_float4(cs[0], cs[1], cs[2], cs[3]);
    ko[1] = make_float4(cs[4], cs[5], cs[6], cs[7]);
}

// One thread per CSR entry: CRYs + observable score (no Rot application).
__global__ void edge_score_kernel(const float* __restrict__ psi,
                                  const float* __restrict__ kcs,
                                  const int* __restrict__ csr_src,
                                  const int* __restrict__ csr_dst, int Et,
                                  const float* __restrict__ attM,
                                  float* __restrict__ att, float* __restrict__ sumptr) {
    int i = blockIdx.x * blockDim.x + threadIdx.x;
    float es = 0.f;
    if (i < Et) {
        int sN = csr_src[i], dN = csr_dst[i];
        float2 s[16];
        const float4* pp = (const float4*)(psi + sN * 32);
#pragma unroll
        for (int j = 0; j < 8; j++) {
            float4 v = pp[j];
            s[2 * j]     = make_float2(v.x, v.y);
            s[2 * j + 1] = make_float2(v.z, v.w);
        }
        float4 cs0 = *(const float4*)(kcs + dN * 8);
        float4 cs1 = *(const float4*)(kcs + dN * 8 + 4);
        ap_cry<8, 4>(s, cs0.x, cs0.y);
        ap_cry<4, 2>(s, cs0.z, cs0.w);
        ap_cry<2, 1>(s, cs1.x, cs1.y);
        ap_cry<1, 8>(s, cs1.z, cs1.w);
        float n[16];
#pragma unroll
        for (int j = 0; j < 16; j++) n[j] = s[j].x * s[j].x + s[j].y * s[j].y;
        float score = 0.f;
        {
            float zd, R, I;
            float4 m;
            m = *(const float4*)(attM + 0);
            pair_sums<8>(s, n, zd, R, I);
            score += m.x * zd + 2.f * (m.y * R - m.z * I);
            m = *(const float4*)(attM + 4);
            pair_sums<4>(s, n, zd, R, I);
            score += m.x * zd + 2.f * (m.y * R - m.z * I);
            m = *(const float4*)(attM + 8);
            pair_sums<2>(s, n, zd, R, I);
            score += m.x * zd + 2.f * (m.y * R - m.z * I);
            m = *(const float4*)(attM + 12);
            pair_sums<1>(s, n, zd, R, I);
            score += m.x * zd + 2.f * (m.y * R - m.z * I);
        }
        es = expf(score * 0.25f);
        att[i] = es;
    }
    float v = es;
#pragma unroll
    for (int off = 16; off; off >>= 1) v += __shfl_xor_sync(0xffffffffu, v, off);
    __shared__ float sred[8];
    int lane = threadIdx.x & 31, warp = threadIdx.x >> 5;
    if (lane == 0) sred[warp] = v;
    __syncthreads();
    if (threadIdx.x == 0) {
        float t = 0.f;
#pragma unroll
        for (int j = 0; j < 8; j++) t += sred[j];
        atomicAdd(sumptr, t);
    }
}

__device__ __forceinline__ float4 ld_half4(const __half* p) {
    uint2 u = *(const uint2*)p;
    __half2 a = *reinterpret_cast<__half2*>(&u.x);
    __half2 b = *reinterpret_cast<__half2*>(&u.y);
    float2 fa = __half22float2(a), fb = __half22float2(b);
    return make_float4(fa.x, fa.y, fb.x, fb.y);
}

// Warp per node: atomic-free fp16 CSR gather + fused ReLU, 4-deep pipelined.
__global__ void aggregate_kernel(const float* __restrict__ att,
                                 const float* __restrict__ sumptr,
                                 const __half* __restrict__ xc,
                                 const int* __restrict__ rowptr,
                                 const int* __restrict__ csr_src,
                                 float* __restrict__ hn, int N) {
    int n = (blockIdx.x * blockDim.x + threadIdx.x) >> 5;
    int lane = threadIdx.x & 31;
    if (n >= N) return;
    int beg = rowptr[n], end = rowptr[n + 1];
    float4 acc = make_float4(0.f, 0.f, 0.f, 0.f);
    int i = beg;
    for (; i + 4 <= end; i += 4) {
        int s0 = csr_src[i],     s1 = csr_src[i + 1];
        int s2 = csr_src[i + 2], s3 = csr_src[i + 3];
        float w0 = att[i],     w1 = att[i + 1];
        float w2 = att[i + 2], w3 = att[i + 3];
        float4 v0 = ld_half4(xc + s0 * 128 + lane * 4);
        float4 v1 = ld_half4(xc + s1 * 128 + lane * 4);
        float4 v2 = ld_half4(xc + s2 * 128 + lane * 4);
        float4 v3 = ld_half4(xc + s3 * 128 + lane * 4);
        acc.x += w0 * v0.x + w1 * v1.x + w2 * v2.x + w3 * v3.x;
        acc.y += w0 * v0.y + w1 * v1.y + w2 * v2.y + w3 * v3.y;
        acc.z += w0 * v0.z + w1 * v1.z + w2 * v2.z + w3 * v3.z;
        acc.w += w0 * v0.w + w1 * v1.w + w2 * v2.w + w3 * v3.w;
    }
    for (; i < end; i++) {
        int s = csr_src[i];
        float w = att[i];
        float4 v = ld_half4(xc + s * 128 + lane * 4);
        acc.x += w * v.x; acc.y += w * v.y; acc.z += w * v.z; acc.w += w * v.w;
    }
    float inv = 1.0f / sumptr[0];
    acc.x = fmaxf(acc.x * inv, 0.f); acc.y = fmaxf(acc.y * inv, 0.f);
    acc.z = fmaxf(acc.z * inv, 0.f); acc.w = fmaxf(acc.w * inv, 0.f);
    *(float4*)(hn + n * 128 + lane * 4) = acc;
}

// Warp per node: pq projection only.
__global__ void path_proj_kernel(const float* __restrict__ h,
                                 const float* __restrict__ piW, const float* __restrict__ pib,
                                 float* __restrict__ pq, int N) {
    int n = (blockIdx.x * blockDim.x + threadIdx.x) >> 5;
    int lane = threadIdx.x & 31;
    if (n >= N) return;
    float4 hv = *(const float4*)(h + n * 128 + lane * 4);
    float acc[4];
#pragma unroll
    for (int j = 0; j < 4; j++) {
        float4 w = *(const float4*)(piW + j * 128 + lane * 4);
        acc[j] = hv.x * w.x + hv.y * w.y + hv.z * w.z + hv.w * w.w;
    }
#pragma unroll
    for (int off = 16; off; off >>= 1)
#pragma unroll
        for (int j = 0; j < 4; j++)
            acc[j] += __shfl_xor_sync(0xffffffffu, acc[j], off);
    if (lane < 4)
        pq[n * 4 + lane] = tanhf(acc[lane] + pib[lane]) * PI_HALF;
}

// Thread per node: path circuit + collapsed epilogue out = c0 + M @ z.
__global__ void path_out_kernel(const float* __restrict__ pq,
                                const float* __restrict__ pathrot,
                                const float* __restrict__ M, const float* __restrict__ c0,
                                float* __restrict__ out, int N) {
    int n = blockIdx.x * blockDim.x + threadIdx.x;
    if (n >= N) return;
    float4 p = *(const float4*)(pq + n * 4);
    float xin[4] = {p.x, p.y, p.z, p.w};
    float z[4];
    path_circ(xin, pathrot, z);
    float4* o4 = (float4*)(out + n * 32);
#pragma unroll
    for (int g = 0; g < 8; g++) {
        float4 r;
        float* rp = (float*)&r;
#pragma unroll
        for (int i = 0; i < 4; i++) {
            int o = g * 4 + i;
            float4 m = *(const float4*)(M + o * 4);
            rp[i] = c0[o] + z[0] * m.x + z[1] * m.y + z[2] * m.z + z[3] * m.w;
        }
        o4[g] = r;
    }
}

// ---------------- host ----------------
extern "C" void kernel_launch(void* const* d_in, const int* in_sizes, int n_in,
                              void* d_out, int out_size) {
    const float* x        = (const float*)d_in[0];
    const float* W_in     = (const float*)d_in[1];
    const float* b_in     = (const float*)d_in[2];
    const float* lin_W    = (const float*)d_in[3];
    const float* lin_b    = (const float*)d_in[4];
    const float* qproj_W  = (const float*)d_in[5];
    const float* qproj_b  = (const float*)d_in[6];
    const float* ent_p    = (const float*)d_in[7];
    const float* attq_W   = (const float*)d_in[8];
    const float* attq_b   = (const float*)d_in[9];
    const float* attk_W   = (const float*)d_in[10];
    const float* attk_b   = (const float*)d_in[11];
    const float* att_qp   = (const float*)d_in[12];
    const float* path_p   = (const float*)d_in[13];
    const float* pi_W     = (const float*)d_in[14];
    const float* pi_b     = (const float*)d_in[15];
    const float* po_W     = (const float*)d_in[16];
    const float* po_b     = (const float*)d_in[17];
    const float* out_W    = (const float*)d_in[18];
    const float* out_b    = (const float*)d_in[19];
    const int*   ei       = (const int*)d_in[20];
    float* out = (float*)d_out;

    int N  = in_sizes[0] / 64;
    int E0 = in_sizes[20] / 2;
    int Et = E0 + N;

    float *bufA, *bufB, *qb, *kb, *zb, *psi, *kcs, *att, *sum, *rot, *attM, *Mp, *c0p;
    float *wt0, *wt1;
    __half* xch;
    int *deg, *rowptr, *cursor, *csrs, *csrd;
    cudaGetSymbolAddress((void**)&bufA,   g_bufA);
    cudaGetSymbolAddress((void**)&bufB,   g_bufB);
    cudaGetSymbolAddress((void**)&xch,    g_xch);
    cudaGetSymbolAddress((void**)&qb,     g_q);
    cudaGetSymbolAddress((void**)&kb,     g_k);
    cudaGetSymbolAddress((void**)&zb,     g_z);
    cudaGetSymbolAddress((void**)&psi,    g_psi);
    cudaGetSymbolAddress((void**)&kcs,    g_kcs);
    cudaGetSymbolAddress((void**)&att,    g_att);
    cudaGetSymbolAddress((void**)&sum,    g_sum);
    cudaGetSymbolAddress((void**)&rot,    g_rot);
    cudaGetSymbolAddress((void**)&attM,   g_attM);
    cudaGetSymbolAddress((void**)&deg,    g_deg);
    cudaGetSymbolAddress((void**)&rowptr, g_rowptr);
    cudaGetSymbolAddress((void**)&cursor, g_cursor);
    cudaGetSymbolAddress((void**)&csrs,   g_csr_src);
    cudaGetSymbolAddress((void**)&csrd,   g_csr_dst);
    cudaGetSymbolAddress((void**)&Mp,     g_M);
    cudaGetSymbolAddress((void**)&c0p,    g_c0);
    cudaGetSymbolAddress((void**)&wt0,    g_Wt0);
    cudaGetSymbolAddress((void**)&wt1,    g_Wt1);

    // one-time stream/event setup (host resources, not device memory)
    static cudaStream_t s1 = nullptr;
    static cudaEvent_t evFork = nullptr, evF[2], evJ[2];
    if (!s1) {
        cudaStreamCreateWithFlags(&s1, cudaStreamNonBlocking);
        cudaEventCreateWithFlags(&evFork, cudaEventDisableTiming);
        for (int i = 0; i < 2; i++) {
            cudaEventCreateWithFlags(&evF[i], cudaEventDisableTiming);
            cudaEventCreateWithFlags(&evJ[i], cudaEventDisableTiming);
        }
    }

    const int SMEM_G64  = (64 * 64 + 64 * 68) * 4;    // 33792
    const int SMEM_G128 = (64 * 128 + 128 * 68) * 4;  // 67584
    cudaFuncSetAttribute(gemm_tile_kernel<64, true, false, false>,
                         cudaFuncAttributeMaxDynamicSharedMemorySize, SMEM_G64);
    cudaFuncSetAttribute(gemm_tile_kernel<128, false, true, true>,
                         cudaFuncAttributeMaxDynamicSharedMemorySize, SMEM_G128);

    // ---- fork s1: CSR build overlaps setup + input GEMM ----
    cudaEventRecord(evFork, 0);
    cudaStreamWaitEvent(s1, evFork, 0);
    cudaMemsetAsync(deg, 0, (size_t)(N + 1) * sizeof(int), s1);
    csr_count_kernel<<<(Et + 255) / 256, 256, 0, s1>>>(ei, E0, N, deg);
    csr_scan_kernel<<<1, 1024, 0, s1>>>(deg, rowptr, cursor, N);
    csr_fill_kernel<<<(Et + 255) / 256, 256, 0, s1>>>(ei, E0, N, cursor, csrs, csrd);

    // ---- stream 0: one fused setup launch + input GEMM ----
    setup_kernel<<<162, 256>>>(W_in, lin_W, att_qp, ent_p, path_p,
                               po_W, po_b, out_W, out_b,
                               wt0, wt1, rot, attM, sum, Mp, c0p);
    {
        dim3 g((N + 63) / 64, 2);
        gemm_tile_kernel<64, true, false, false><<<g, 256, SMEM_G64>>>(
            x, wt0, b_in, nullptr, nullptr, nullptr, bufA, nullptr, N);
    }

    float* hcur = bufA;
    float* hnext = bufB;
    for (int l = 0; l < 2; l++) {
        // fork: edge chain on s1 (needs only hcur + csr + attM)
        cudaEventRecord(evF[l], 0);
        cudaStreamWaitEvent(s1, evF[l], 0);
        qk_proj_kernel<<<(N * 32 + 255) / 256, 256, 0, s1>>>(
            hcur, attq_W + l * 4 * 128, attq_b + l * 4,
            attk_W + l * 4 * 128, attk_b + l * 4, qb, kb, N);
        edge_prep_kernel<<<(N + 127) / 128, 128, 0, s1>>>(qb, kb, psi, kcs, N);
        edge_score_kernel<<<(Et + 255) / 256, 256, 0, s1>>>(
            psi, kcs, csrs, csrd, Et, attM + l * 16, att, sum + l);
        cudaEventRecord(evJ[l], s1);

        // stream 0: ent circuit then GEMM with fused z-projection -> fp16 xc
        ent_kernel<<<(N + 127) / 128, 128>>>(hcur, rot + 64 + l * 64, zb, N);
        {
            dim3 g((N + 63) / 64, 2);
            gemm_tile_kernel<128, false, true, true><<<g, 256, SMEM_G128>>>(
                hcur, wt1 + l * 128 * 128, lin_b + l * 128,
                zb, qproj_W + l * 128 * 4, qproj_b + l * 128, nullptr, xch, N);
        }

        // join, then aggregate
        cudaStreamWaitEvent(0, evJ[l], 0);
        aggregate_kernel<<<(N * 32 + 255) / 256, 256>>>(
            att, sum + l, xch, rowptr, csrs, hnext, N);
        float* t = hcur; hcur = hnext; hnext = t;
    }

    path_proj_kernel<<<(N * 32 + 255) / 256, 256>>>(hcur, pi_W, pi_b, qb, N);
    path_out_kernel<<<(N + 127) / 128, 128>>>(qb, rot + 192, Mp, c0p, out, N);
}